// round 10
// baseline (speedup 1.0000x reference)
#include <cuda_runtime.h>
#include <cuda_bf16.h>
#include <cuda_fp8.h>
#include <cstdint>

// Problem constants
// B=4, C=64, H=W=64, PS=4, PD=1, UFSTRIDE=2, STRIDE=1, SCALE=10
// L = 1024 (M), hs=ws=63, P = 3969 (N, padded 4096), K = 1024
// Split: main = ahi*bhi (bf16, K=1024); cross = ahi*blo + alo*bhi (e4m3, K=2048, 2^16-scaled)

#define NB    4
#define NC    64
#define LL    1024
#define KK    1024
#define PP    3969
#define PPAD  4096
#define CSTR  3972

// GEMM tiling — both GEMMs use 2048-byte K-rows, 128-byte chunks
#define BM    128
#define BN    256
#define NCHUNK 16
#define ABYTES (BM * 128)           // 16384
#define BBYTES (BN * 128)           // 32768
#define BUFBYTES (ABYTES + BBYTES)  // 49152
#define NSTAGE 3
#define SM_BYTES (NSTAGE * BUFBYTES) // 147456

static __device__ float d_invn[NB * NC];
static __device__ __align__(16) __nv_bfloat16 d_Am[(size_t)NB * LL * KK];     // [b][l][k] hi
static __device__ __align__(16) __nv_bfloat16 d_Fm[(size_t)NB * PPAD * KK];   // [b][p][k] hi
static __device__ __align__(16) uint8_t d_Ax[(size_t)NB * LL * 2 * KK];       // [16*ahi | 4096*alo]
static __device__ __align__(16) uint8_t d_Fx[(size_t)NB * PPAD * 2 * KK];     // [4096*blo | 16*bhi]
static __device__ float d_cos [(size_t)NB * LL * CSTR];
static __device__ float d_tmp [(size_t)NB * LL * CSTR];
static __device__ float d_mmk [NB * LL];
static __device__ float d_mmp [NB * PP];
static __device__ float d_maxv[NB * PP];
static __device__ float d_rcps[NB * PP];

__device__ __forceinline__ int clamp64(int v) { return min(max(v, 0), 63); }

__device__ __forceinline__ uint32_t smem_u32(const void* p) {
    uint32_t a;
    asm("{ .reg .u64 t; cvta.to.shared.u64 t, %1; cvt.u32.u64 %0, t; }" : "=r"(a) : "l"(p));
    return a;
}
__device__ __forceinline__ void cp_async16(uint32_t dst, const void* src) {
    asm volatile("cp.async.cg.shared.global [%0], [%1], 16;" :: "r"(dst), "l"(src) : "memory");
}
__device__ __forceinline__ void ldsm_x4(uint32_t* r, uint32_t addr) {
    asm volatile("ldmatrix.sync.aligned.m8n8.x4.shared.b16 {%0,%1,%2,%3}, [%4];"
                 : "=r"(r[0]), "=r"(r[1]), "=r"(r[2]), "=r"(r[3]) : "r"(addr));
}
__device__ __forceinline__ void mma_bf16(float* c, const uint32_t* a, const uint32_t* b) {
    asm volatile(
        "mma.sync.aligned.m16n8k16.row.col.f32.bf16.bf16.f32 "
        "{%0,%1,%2,%3}, {%4,%5,%6,%7}, {%8,%9}, {%0,%1,%2,%3};"
        : "+f"(c[0]), "+f"(c[1]), "+f"(c[2]), "+f"(c[3])
        : "r"(a[0]), "r"(a[1]), "r"(a[2]), "r"(a[3]), "r"(b[0]), "r"(b[1]));
}
__device__ __forceinline__ void mma_fp8(float* c, const uint32_t* a, const uint32_t* b) {
    asm volatile(
        "mma.sync.aligned.m16n8k32.row.col.f32.e4m3.e4m3.f32 "
        "{%0,%1,%2,%3}, {%4,%5,%6,%7}, {%8,%9}, {%0,%1,%2,%3};"
        : "+f"(c[0]), "+f"(c[1]), "+f"(c[2]), "+f"(c[3])
        : "r"(a[0]), "r"(a[1]), "r"(a[2]), "r"(a[3]), "r"(b[0]), "r"(b[1]));
}
// swizzled smem offset: row r (128 B), 16-byte column c
__device__ __forceinline__ uint32_t swz(uint32_t base, int r, int c) {
    return base + r * 128 + ((c ^ (r & 7)) << 4);
}

// ---------------------------------------------------------------------------
// 1) per-(b,c) inverse L2 norm of b
// ---------------------------------------------------------------------------
__global__ void norm_kernel(const float* __restrict__ bsrc) {
    int bc = blockIdx.x;
    const float* src = bsrc + (size_t)bc * 4096;
    float s = 0.f;
    for (int i = threadIdx.x; i < 4096; i += 256) {
        float v = src[i];
        s += v * v;
    }
    __shared__ float sh[256];
    sh[threadIdx.x] = s;
    __syncthreads();
    for (int o = 128; o > 0; o >>= 1) {
        if (threadIdx.x < o) sh[threadIdx.x] += sh[threadIdx.x + o];
        __syncthreads();
    }
    if (threadIdx.x == 0) d_invn[bc] = 1.0f / sqrtf(sh[0] + 1e-8f);
}

// ---------------------------------------------------------------------------
// 2) build A: bf16 hi + fp8 cross segs
// ---------------------------------------------------------------------------
__global__ void build_A(const float* __restrict__ bsrc) {
    int idx = blockIdx.x * 256 + threadIdx.x;
    int k  = idx & 1023;
    int l  = (idx >> 10) & 1023;
    int bI = idx >> 20;
    int c  = k >> 4, i = (k >> 2) & 3, j = k & 3;
    int ly = l >> 5, lx = l & 31;
    int h = clamp64(2 * ly + i - 1);
    int w = clamp64(2 * lx + j - 1);
    float a = bsrc[((size_t)(bI * NC + c)) * 4096 + h * 64 + w] * d_invn[bI * NC + c];
    __nv_bfloat16 hi = __float2bfloat16(a);
    float hif = __bfloat162float(hi);
    float lo = a - hif;
    d_Am[(size_t)(bI * LL + l) * KK + k] = hi;
    size_t xb = (size_t)(bI * LL + l) * 2048;
    d_Ax[xb + k]        = __nv_fp8_e4m3(16.0f * hif).__x;
    d_Ax[xb + 1024 + k] = __nv_fp8_e4m3(4096.0f * lo).__x;
}

// ---------------------------------------------------------------------------
// 3) build F (im2col): bf16 hi + fp8 cross segs
// ---------------------------------------------------------------------------
__global__ void build_F(const float* __restrict__ fsrc) {
    int idx = blockIdx.x * 256 + threadIdx.x;
    int k  = idx & 1023;
    int p  = (idx >> 10) & 4095;
    int bI = idx >> 22;
    float v = 0.f;
    if (p < PP) {
        int y = p / 63, x = p - 63 * y;
        int c = k >> 4, i = (k >> 2) & 3, j = k & 3;
        int h = clamp64(y + i - 1);
        int w = clamp64(x + j - 1);
        v = fsrc[((size_t)(bI * NC + c)) * 4096 + h * 64 + w];
    }
    __nv_bfloat16 hi = __float2bfloat16(v);
    float hif = __bfloat162float(hi);
    float lo = v - hif;
    d_Fm[((size_t)bI * PPAD + p) * KK + k] = hi;
    size_t xb = ((size_t)bI * PPAD + p) * 2048;
    d_Fx[xb + k]        = __nv_fp8_e4m3(4096.0f * lo).__x;
    d_Fx[xb + 1024 + k] = __nv_fp8_e4m3(16.0f * hif).__x;
}

// ---------------------------------------------------------------------------
// 4/5) mask means
// ---------------------------------------------------------------------------
__global__ void mmk_kernel(const float* __restrict__ mask) {
    int idx = blockIdx.x * 256 + threadIdx.x;
    int l = idx & 1023, b = idx >> 10;
    int ly = l >> 5, lx = l & 31;
    const float* m = mask + (size_t)b * 4096;
    float s = 0.f;
    #pragma unroll
    for (int i = 0; i < 4; i++)
        #pragma unroll
        for (int j = 0; j < 4; j++)
            s += 1.0f - m[clamp64(2 * ly + i - 1) * 64 + clamp64(2 * lx + j - 1)];
    d_mmk[idx] = s * 0.0625f;
}
__global__ void mmp_kernel(const float* __restrict__ mask) {
    int p = blockIdx.x * 256 + threadIdx.x;
    if (p >= PP) return;
    int b = blockIdx.y;
    int y = p / 63, x = p - 63 * y;
    const float* m = mask + (size_t)b * 4096;
    float s = 0.f;
    #pragma unroll
    for (int i = 0; i < 4; i++)
        #pragma unroll
        for (int j = 0; j < 4; j++)
            s += 1.0f - m[clamp64(y + i - 1) * 64 + clamp64(x + j - 1)];
    d_mmp[b * PP + p] = s * 0.0625f;
}

// ---------------------------------------------------------------------------
// 6a) fp8 cross GEMM: d_cos = 2^-16 * sum_k' Ax*Fx   (runs FIRST)
//     128x256 CTA tile, 3-stage cp.async, warp 64x64, m16n8k32 e4m3
// ---------------------------------------------------------------------------
__global__ void __launch_bounds__(256, 1)
gemm_fp8_kernel() {
    extern __shared__ char smem[];
    const uint32_t sb = smem_u32(smem);
    const int tid  = threadIdx.x;
    const int wid  = tid >> 5;
    const int lane = tid & 31;
    const int wm   = wid >> 2;
    const int wn   = wid & 3;
    const int bI = blockIdx.z;
    const int m0 = blockIdx.y * BM;
    const int n0 = blockIdx.x * BN;

    const char* Ag = (const char*)d_Ax + ((size_t)bI * LL   + m0) * 2048;
    const char* Bg = (const char*)d_Fx + ((size_t)bI * PPAD + n0) * 2048;

    float acc[4][8][4];
    #pragma unroll
    for (int mt = 0; mt < 4; mt++)
        #pragma unroll
        for (int nt = 0; nt < 8; nt++)
            #pragma unroll
            for (int e = 0; e < 4; e++) acc[mt][nt][e] = 0.f;

    const int ar = wm * 64 + (lane & 15);
    const int ac = (lane >> 4);
    const int br = wn * 64 + (lane & 7) + ((lane >> 4) << 3);
    const int bc = (lane >> 3) & 1;

    auto load_chunk = [&](int ch, int buf) {
        const uint32_t ab = sb + buf * BUFBYTES;
        const uint32_t bb = ab + ABYTES;
        const size_t koff = (size_t)ch * 128;
        #pragma unroll
        for (int i = 0; i < 4; i++) {
            int idx = i * 256 + tid;
            int r = idx >> 3, c = idx & 7;
            cp_async16(swz(ab, r, c), Ag + (size_t)r * 2048 + koff + c * 16);
        }
        #pragma unroll
        for (int i = 0; i < 8; i++) {
            int idx = i * 256 + tid;
            int r = idx >> 3, c = idx & 7;
            cp_async16(swz(bb, r, c), Bg + (size_t)r * 2048 + koff + c * 16);
        }
        asm volatile("cp.async.commit_group;" ::: "memory");
    };

    load_chunk(0, 0);
    load_chunk(1, 1);
    load_chunk(2, 2);

    int buf = 0;
    for (int ch = 0; ch < NCHUNK; ch++) {
        if (ch < NCHUNK - 2)       asm volatile("cp.async.wait_group 2;" ::: "memory");
        else if (ch == NCHUNK - 2) asm volatile("cp.async.wait_group 1;" ::: "memory");
        else                       asm volatile("cp.async.wait_group 0;" ::: "memory");
        __syncthreads();

        const uint32_t ab = sb + buf * BUFBYTES;
        const uint32_t bb = ab + ABYTES;
        #pragma unroll
        for (int ks = 0; ks < 4; ks++) {       // k32 per step, 2 x 16B cols
            uint32_t afr[4][4];
            #pragma unroll
            for (int mt = 0; mt < 4; mt++)
                ldsm_x4(afr[mt], swz(ab, ar + mt * 16, ks * 2 + ac));
            uint32_t bfr[8][2];
            #pragma unroll
            for (int pp = 0; pp < 4; pp++) {
                uint32_t t[4];
                ldsm_x4(t, swz(bb, br + pp * 16, ks * 2 + bc));
                bfr[2 * pp][0] = t[0]; bfr[2 * pp][1] = t[1];
                bfr[2 * pp + 1][0] = t[2]; bfr[2 * pp + 1][1] = t[3];
            }
            #pragma unroll
            for (int mt = 0; mt < 4; mt++)
                #pragma unroll
                for (int nt = 0; nt < 8; nt++)
                    mma_fp8(acc[mt][nt], afr[mt], bfr[nt]);
        }
        __syncthreads();
        if (ch + NSTAGE < NCHUNK) load_chunk(ch + NSTAGE, buf);
        buf = (buf == NSTAGE - 1) ? 0 : buf + 1;
    }

    const float sc = 1.0f / 65536.0f;
    #pragma unroll
    for (int mt = 0; mt < 4; mt++) {
        int mrow = m0 + wm * 64 + mt * 16 + (lane >> 2);
        float* C0 = d_cos + ((size_t)(bI * LL + mrow)) * CSTR;
        float* C1 = C0 + (size_t)8 * CSTR;
        #pragma unroll
        for (int nt = 0; nt < 8; nt++) {
            int n = n0 + wn * 64 + nt * 8 + 2 * (lane & 3);
            if (n + 1 < PP) {
                *(float2*)&C0[n] = make_float2(acc[mt][nt][0] * sc, acc[mt][nt][1] * sc);
                *(float2*)&C1[n] = make_float2(acc[mt][nt][2] * sc, acc[mt][nt][3] * sc);
            } else if (n < PP) {
                C0[n] = acc[mt][nt][0] * sc;
                C1[n] = acc[mt][nt][2] * sc;
            }
        }
    }
}

// ---------------------------------------------------------------------------
// 6b) bf16 main GEMM: d_cos += sum_k Am*Fm    (runs SECOND, read-add-write)
// ---------------------------------------------------------------------------
__global__ void __launch_bounds__(256, 1)
gemm_bf16_kernel() {
    extern __shared__ char smem[];
    const uint32_t sb = smem_u32(smem);
    const int tid  = threadIdx.x;
    const int wid  = tid >> 5;
    const int lane = tid & 31;
    const int wm   = wid >> 2;
    const int wn   = wid & 3;
    const int bI = blockIdx.z;
    const int m0 = blockIdx.y * BM;
    const int n0 = blockIdx.x * BN;

    const char* Ag = (const char*)d_Am + ((size_t)bI * LL   + m0) * 2048;
    const char* Bg = (const char*)d_Fm + ((size_t)bI * PPAD + n0) * 2048;

    float acc[4][8][4];
    #pragma unroll
    for (int mt = 0; mt < 4; mt++)
        #pragma unroll
        for (int nt = 0; nt < 8; nt++)
            #pragma unroll
            for (int e = 0; e < 4; e++) acc[mt][nt][e] = 0.f;

    const int ar = wm * 64 + (lane & 15);
    const int ac = (lane >> 4);
    const int br = wn * 64 + (lane & 7) + ((lane >> 4) << 3);
    const int bc = (lane >> 3) & 1;

    auto load_chunk = [&](int ch, int buf) {
        const uint32_t ab = sb + buf * BUFBYTES;
        const uint32_t bb = ab + ABYTES;
        const size_t koff = (size_t)ch * 128;
        #pragma unroll
        for (int i = 0; i < 4; i++) {
            int idx = i * 256 + tid;
            int r = idx >> 3, c = idx & 7;
            cp_async16(swz(ab, r, c), Ag + (size_t)r * 2048 + koff + c * 16);
        }
        #pragma unroll
        for (int i = 0; i < 8; i++) {
            int idx = i * 256 + tid;
            int r = idx >> 3, c = idx & 7;
            cp_async16(swz(bb, r, c), Bg + (size_t)r * 2048 + koff + c * 16);
        }
        asm volatile("cp.async.commit_group;" ::: "memory");
    };

    load_chunk(0, 0);
    load_chunk(1, 1);
    load_chunk(2, 2);

    int buf = 0;
    for (int ch = 0; ch < NCHUNK; ch++) {
        if (ch < NCHUNK - 2)       asm volatile("cp.async.wait_group 2;" ::: "memory");
        else if (ch == NCHUNK - 2) asm volatile("cp.async.wait_group 1;" ::: "memory");
        else                       asm volatile("cp.async.wait_group 0;" ::: "memory");
        __syncthreads();

        const uint32_t ab = sb + buf * BUFBYTES;
        const uint32_t bb = ab + ABYTES;
        #pragma unroll
        for (int ks = 0; ks < 4; ks++) {       // k16 per step (64 bf16 per chunk row)
            uint32_t afr[4][4];
            #pragma unroll
            for (int mt = 0; mt < 4; mt++)
                ldsm_x4(afr[mt], swz(ab, ar + mt * 16, ks * 2 + ac));
            uint32_t bfr[8][2];
            #pragma unroll
            for (int pp = 0; pp < 4; pp++) {
                uint32_t t[4];
                ldsm_x4(t, swz(bb, br + pp * 16, ks * 2 + bc));
                bfr[2 * pp][0] = t[0]; bfr[2 * pp][1] = t[1];
                bfr[2 * pp + 1][0] = t[2]; bfr[2 * pp + 1][1] = t[3];
            }
            #pragma unroll
            for (int mt = 0; mt < 4; mt++)
                #pragma unroll
                for (int nt = 0; nt < 8; nt++)
                    mma_bf16(acc[mt][nt], afr[mt], bfr[nt]);
        }
        __syncthreads();
        if (ch + NSTAGE < NCHUNK) load_chunk(ch + NSTAGE, buf);
        buf = (buf == NSTAGE - 1) ? 0 : buf + 1;
    }

    // epilogue: add cross contribution already in d_cos
    #pragma unroll
    for (int mt = 0; mt < 4; mt++) {
        int mrow = m0 + wm * 64 + mt * 16 + (lane >> 2);
        float* C0 = d_cos + ((size_t)(bI * LL + mrow)) * CSTR;
        float* C1 = C0 + (size_t)8 * CSTR;
        #pragma unroll
        for (int nt = 0; nt < 8; nt++) {
            int n = n0 + wn * 64 + nt * 8 + 2 * (lane & 3);
            if (n + 1 < PP) {
                float2 o0 = *(float2*)&C0[n];
                float2 o1 = *(float2*)&C1[n];
                *(float2*)&C0[n] = make_float2(o0.x + acc[mt][nt][0], o0.y + acc[mt][nt][1]);
                *(float2*)&C1[n] = make_float2(o1.x + acc[mt][nt][2], o1.y + acc[mt][nt][3]);
            } else if (n < PP) {
                C0[n] += acc[mt][nt][0];
                C1[n] += acc[mt][nt][2];
            }
        }
    }
}

// ---------------------------------------------------------------------------
// 7) pass1: diag3 on flat (1024, 3969)
// ---------------------------------------------------------------------------
__global__ void pass1_kernel() {
    int q = blockIdx.x * 256 + threadIdx.x;
    if (q >= PP) return;
    int br = blockIdx.y;
    const float* base = d_cos + (size_t)(br >> 10) * LL * CSTR;
    int r = br & 1023;
    float s = base[(size_t)r * CSTR + q];
    if (r > 0 && q > 0)         s += base[(size_t)(r - 1) * CSTR + q - 1];
    if (r < 1023 && q < PP - 1) s += base[(size_t)(r + 1) * CSTR + q + 1];
    d_tmp[(size_t)br * CSTR + q] = s;
}

// ---------------------------------------------------------------------------
// 8) pass2: transposed-view diag3 + mask, back into d_cos
// ---------------------------------------------------------------------------
__global__ void pass2_kernel() {
    int q = blockIdx.x * 256 + threadIdx.x;
    if (q >= PP) return;
    int br = blockIdx.y;
    int b = br >> 10;
    int r = br & 1023;
    int ly = r >> 5, lx = r & 31;
    int r2 = lx * 32 + ly;
    int y = q / 63, x = q - 63 * y;
    int q2 = x * 63 + y;
    const float* tb = d_tmp + (size_t)b * LL * CSTR;
    float s = 0.f;
    #pragma unroll
    for (int d = -1; d <= 1; d++) {
        int rr = r2 + d, qq = q2 + d;
        if (rr >= 0 && rr < 1024 && qq >= 0 && qq < PP) {
            int lx2 = rr >> 5, ly2 = rr & 31;
            int x2 = qq / 63, y2 = qq - 63 * x2;
            s += tb[(size_t)(ly2 * 32 + lx2) * CSTR + (y2 * 63 + x2)];
        }
    }
    float mk = d_mmk[b * LL + r];
    float mp = d_mmp[b * PP + q];
    float mm = ((mk > mp && mp > 0.5f) || (mk == 1.0f)) ? 1.0f : 0.0f;
    d_cos[(size_t)br * CSTR + q] = s * mm;
}

// ---------------------------------------------------------------------------
// 9) softmax reduce over l
// ---------------------------------------------------------------------------
__global__ void smax_reduce_kernel() {
    int b  = blockIdx.y;
    int pl = threadIdx.x & 31;
    int lt = threadIdx.x >> 5;
    int p  = blockIdx.x * 32 + pl;
    float m = -1e30f, s = 0.f;
    if (p < PP) {
        const float* cf = d_cos + (size_t)b * LL * CSTR + p;
        for (int l = lt; l < LL; l += 8) {
            float x = 10.0f * cf[(size_t)l * CSTR];
            float mn = fmaxf(m, x);
            s = s * __expf(m - mn) + __expf(x - mn);
            m = mn;
        }
    }
    __shared__ float shm[8][32], shs[8][32];
    shm[lt][pl] = m;
    shs[lt][pl] = s;
    __syncthreads();
    if (lt == 0 && p < PP) {
        float M = shm[0][pl];
        #pragma unroll
        for (int t = 1; t < 8; t++) M = fmaxf(M, shm[t][pl]);
        float S = 0.f;
        #pragma unroll
        for (int t = 0; t < 8; t++) S += shs[t][pl] * __expf(shm[t][pl] - M);
        d_maxv[b * PP + p] = M;
        d_rcps[b * PP + p] = 1.0f / S;
    }
}

// ---------------------------------------------------------------------------
// 10) softmax write
// ---------------------------------------------------------------------------
__global__ void smax_write_kernel(float* __restrict__ out) {
    int q = blockIdx.x * 256 + threadIdx.x;
    if (q >= PP) return;
    int bl = blockIdx.y;
    int b = bl >> 10;
    float x = 10.0f * d_cos[(size_t)bl * CSTR + q];
    out[(size_t)bl * PP + q] = __expf(x - d_maxv[b * PP + q]) * d_rcps[b * PP + q];
}

// ---------------------------------------------------------------------------
extern "C" void kernel_launch(void* const* d_in, const int* in_sizes, int n_in,
                              void* d_out, int out_size) {
    const float* f    = (const float*)d_in[0];
    const float* bsrc = (const float*)d_in[1];
    const float* mask = (const float*)d_in[2];
    float* out = (float*)d_out;

    cudaFuncSetAttribute(gemm_fp8_kernel,
                         cudaFuncAttributeMaxDynamicSharedMemorySize, SM_BYTES);
    cudaFuncSetAttribute(gemm_bf16_kernel,
                         cudaFuncAttributeMaxDynamicSharedMemorySize, SM_BYTES);

    norm_kernel<<<NB * NC, 256>>>(bsrc);
    build_A<<<(NB * KK * LL) / 256, 256>>>(bsrc);
    build_F<<<(NB * PPAD * KK) / 256, 256>>>(f);
    mmk_kernel<<<(NB * LL) / 256, 256>>>(mask);
    mmp_kernel<<<dim3((PP + 255) / 256, NB), 256>>>(mask);

    gemm_fp8_kernel<<<dim3(PPAD / BN, LL / BM, NB), 256, SM_BYTES>>>();
    gemm_bf16_kernel<<<dim3(PPAD / BN, LL / BM, NB), 256, SM_BYTES>>>();

    dim3 g2((PP + 255) / 256, NB * LL);
    pass1_kernel<<<g2, 256>>>();
    pass2_kernel<<<g2, 256>>>();

    smax_reduce_kernel<<<dim3((PP + 31) / 32, NB), 256>>>();
    smax_write_kernel<<<g2, 256>>>(out);
}

// round 11
// speedup vs baseline: 1.2185x; 1.2185x over previous
#include <cuda_runtime.h>
#include <cuda_bf16.h>
#include <cstdint>

// Problem constants
// B=4, C=64, H=W=64, PS=4, PD=1, UFSTRIDE=2, STRIDE=1, SCALE=10
// Factorization: T[u,v,ys,xs] = sum_c bn[c,u,v] * f[c,ys,xs]   (GEMM, K=64)
//   cos[ly,lx,y,x] = sum_{dy,dx} T[cl(2ly+dy-1), cl(2lx+dx-1), cl(y+dy-1), cl(x+dx-1)]
// computed separably: stage1 sums dx (T->V), stage2 sums dy (V->cos).

#define NB    4
#define NC    64
#define LL    1024
#define PP    3969
#define CSTR  3972
#define SPA   4096         // 64*64 spatial positions (GEMM M and N)
#define GKS   192          // 3-split K = 3*64
#define ROWB  384          // bytes per split row (192 bf16)

// GEMM tiling
#define BM    128
#define BN    256
#define NCHUNK 3
#define ABYTES (BM * 128)
#define BBYTES (BN * 128)
#define BUFBYTES (ABYTES + BBYTES)   // 49152
#define NSTAGE 3
#define SM_BYTES (NSTAGE * BUFBYTES) // 147456
#define S2_SMEM (4 * 4032 * 4)       // stage2: 4 planes of 64x63 f32 = 64512

static __device__ float d_invn[NB * NC];
static __device__ __align__(16) __nv_bfloat16 d_A2[(size_t)NB * SPA * GKS];  // bn split [hi,hi,lo]
static __device__ __align__(16) __nv_bfloat16 d_F2[(size_t)NB * SPA * GKS];  // f  split [hi,lo,hi]
static __device__ float d_T  [(size_t)NB * SPA * SPA];                        // 268 MB
static __device__ float d_V  [(size_t)NB * 64 * 32 * 64 * 63];                // 132 MB
static __device__ float d_cos [(size_t)NB * LL * CSTR];
static __device__ float d_tmp [(size_t)NB * LL * CSTR];
static __device__ float d_mmk [NB * LL];
static __device__ float d_mmp [NB * PP];
static __device__ float d_maxv[NB * PP];
static __device__ float d_rcps[NB * PP];

__device__ __forceinline__ int clamp64(int v) { return min(max(v, 0), 63); }

__device__ __forceinline__ uint32_t smem_u32(const void* p) {
    uint32_t a;
    asm("{ .reg .u64 t; cvta.to.shared.u64 t, %1; cvt.u32.u64 %0, t; }" : "=r"(a) : "l"(p));
    return a;
}
__device__ __forceinline__ void cp_async16(uint32_t dst, const void* src) {
    asm volatile("cp.async.cg.shared.global [%0], [%1], 16;" :: "r"(dst), "l"(src) : "memory");
}
__device__ __forceinline__ void ldsm_x4(uint32_t* r, uint32_t addr) {
    asm volatile("ldmatrix.sync.aligned.m8n8.x4.shared.b16 {%0,%1,%2,%3}, [%4];"
                 : "=r"(r[0]), "=r"(r[1]), "=r"(r[2]), "=r"(r[3]) : "r"(addr));
}
__device__ __forceinline__ void mma_bf16(float* c, const uint32_t* a, const uint32_t* b) {
    asm volatile(
        "mma.sync.aligned.m16n8k16.row.col.f32.bf16.bf16.f32 "
        "{%0,%1,%2,%3}, {%4,%5,%6,%7}, {%8,%9}, {%0,%1,%2,%3};"
        : "+f"(c[0]), "+f"(c[1]), "+f"(c[2]), "+f"(c[3])
        : "r"(a[0]), "r"(a[1]), "r"(a[2]), "r"(a[3]), "r"(b[0]), "r"(b[1]));
}
__device__ __forceinline__ uint32_t swz(uint32_t base, int r, int c) {
    return base + r * 128 + ((c ^ (r & 7)) << 4);
}

// ---------------------------------------------------------------------------
// 1) per-(b,c) inverse L2 norm of b
// ---------------------------------------------------------------------------
__global__ void norm_kernel(const float* __restrict__ bsrc) {
    int bc = blockIdx.x;
    const float* src = bsrc + (size_t)bc * 4096;
    float s = 0.f;
    for (int i = threadIdx.x; i < 4096; i += 256) {
        float v = src[i];
        s += v * v;
    }
    __shared__ float sh[256];
    sh[threadIdx.x] = s;
    __syncthreads();
    for (int o = 128; o > 0; o >>= 1) {
        if (threadIdx.x < o) sh[threadIdx.x] += sh[threadIdx.x + o];
        __syncthreads();
    }
    if (threadIdx.x == 0) d_invn[bc] = 1.0f / sqrtf(sh[0] + 1e-8f);
}

// ---------------------------------------------------------------------------
// 2) build bn split A2[b][s=u*64+v][seg*64+c], segs [hi,hi,lo]
// ---------------------------------------------------------------------------
__global__ void build_bn_split(const float* __restrict__ bsrc) {
    int idx = blockIdx.x * 256 + threadIdx.x;     // NB*4096*64
    int c = idx & 63;
    int s = (idx >> 6) & 4095;
    int b = idx >> 18;
    float a = bsrc[((size_t)(b * NC + c)) * 4096 + s] * d_invn[b * NC + c];
    __nv_bfloat16 hi = __float2bfloat16(a);
    __nv_bfloat16 lo = __float2bfloat16(a - __bfloat162float(hi));
    size_t row = ((size_t)b * SPA + s) * GKS;
    d_A2[row + c]        = hi;
    d_A2[row + 64 + c]   = hi;
    d_A2[row + 128 + c]  = lo;
}

// ---------------------------------------------------------------------------
// 3) build f split F2[b][s][seg*64+c], segs [hi,lo,hi]
// ---------------------------------------------------------------------------
__global__ void build_f_split(const float* __restrict__ fsrc) {
    int idx = blockIdx.x * 256 + threadIdx.x;
    int c = idx & 63;
    int s = (idx >> 6) & 4095;
    int b = idx >> 18;
    float v = fsrc[((size_t)(b * NC + c)) * 4096 + s];
    __nv_bfloat16 hi = __float2bfloat16(v);
    __nv_bfloat16 lo = __float2bfloat16(v - __bfloat162float(hi));
    size_t row = ((size_t)b * SPA + s) * GKS;
    d_F2[row + c]        = hi;
    d_F2[row + 64 + c]   = lo;
    d_F2[row + 128 + c]  = hi;
}

// ---------------------------------------------------------------------------
// 4/5) mask means
// ---------------------------------------------------------------------------
__global__ void mmk_kernel(const float* __restrict__ mask) {
    int idx = blockIdx.x * 256 + threadIdx.x;
    int l = idx & 1023, b = idx >> 10;
    int ly = l >> 5, lx = l & 31;
    const float* m = mask + (size_t)b * 4096;
    float s = 0.f;
    #pragma unroll
    for (int i = 0; i < 4; i++)
        #pragma unroll
        for (int j = 0; j < 4; j++)
            s += 1.0f - m[clamp64(2 * ly + i - 1) * 64 + clamp64(2 * lx + j - 1)];
    d_mmk[idx] = s * 0.0625f;
}
__global__ void mmp_kernel(const float* __restrict__ mask) {
    int p = blockIdx.x * 256 + threadIdx.x;
    if (p >= PP) return;
    int b = blockIdx.y;
    int y = p / 63, x = p - 63 * y;
    const float* m = mask + (size_t)b * 4096;
    float s = 0.f;
    #pragma unroll
    for (int i = 0; i < 4; i++)
        #pragma unroll
        for (int j = 0; j < 4; j++)
            s += 1.0f - m[clamp64(y + i - 1) * 64 + clamp64(x + j - 1)];
    d_mmp[b * PP + p] = s * 0.0625f;
}

// ---------------------------------------------------------------------------
// 6) bf16 3-split GEMM: T[b][m][n] = sum_k A2[b][m][k] * F2[b][n][k]
//    M=N=4096, K=192 (3 chunks of 64). 128x256 CTA tile, warp 64x64.
// ---------------------------------------------------------------------------
__global__ void __launch_bounds__(256, 1)
gemm_T_kernel() {
    extern __shared__ char smem[];
    const uint32_t sb = smem_u32(smem);
    const int tid  = threadIdx.x;
    const int wid  = tid >> 5;
    const int lane = tid & 31;
    const int wm   = wid >> 2;
    const int wn   = wid & 3;
    const int bI = blockIdx.z;
    const int m0 = blockIdx.y * BM;
    const int n0 = blockIdx.x * BN;

    const char* Ag = (const char*)d_A2 + ((size_t)bI * SPA + m0) * ROWB;
    const char* Bg = (const char*)d_F2 + ((size_t)bI * SPA + n0) * ROWB;

    float acc[4][8][4];
    #pragma unroll
    for (int mt = 0; mt < 4; mt++)
        #pragma unroll
        for (int nt = 0; nt < 8; nt++)
            #pragma unroll
            for (int e = 0; e < 4; e++) acc[mt][nt][e] = 0.f;

    const int ar = wm * 64 + (lane & 15);
    const int ac = (lane >> 4);
    const int br = wn * 64 + (lane & 7) + ((lane >> 4) << 3);
    const int bc = (lane >> 3) & 1;

    auto load_chunk = [&](int ch, int buf) {
        const uint32_t ab = sb + buf * BUFBYTES;
        const uint32_t bb = ab + ABYTES;
        const size_t koff = (size_t)ch * 128;
        #pragma unroll
        for (int i = 0; i < 4; i++) {
            int idx = i * 256 + tid;
            int r = idx >> 3, c = idx & 7;
            cp_async16(swz(ab, r, c), Ag + (size_t)r * ROWB + koff + c * 16);
        }
        #pragma unroll
        for (int i = 0; i < 8; i++) {
            int idx = i * 256 + tid;
            int r = idx >> 3, c = idx & 7;
            cp_async16(swz(bb, r, c), Bg + (size_t)r * ROWB + koff + c * 16);
        }
        asm volatile("cp.async.commit_group;" ::: "memory");
    };

    load_chunk(0, 0);
    load_chunk(1, 1);
    load_chunk(2, 2);

    int buf = 0;
    for (int ch = 0; ch < NCHUNK; ch++) {
        if (ch < NCHUNK - 2)       asm volatile("cp.async.wait_group 2;" ::: "memory");
        else if (ch == NCHUNK - 2) asm volatile("cp.async.wait_group 1;" ::: "memory");
        else                       asm volatile("cp.async.wait_group 0;" ::: "memory");
        __syncthreads();

        const uint32_t ab = sb + buf * BUFBYTES;
        const uint32_t bb = ab + ABYTES;
        #pragma unroll
        for (int ks = 0; ks < 4; ks++) {
            uint32_t afr[4][4];
            #pragma unroll
            for (int mt = 0; mt < 4; mt++)
                ldsm_x4(afr[mt], swz(ab, ar + mt * 16, ks * 2 + ac));
            uint32_t bfr[8][2];
            #pragma unroll
            for (int pp = 0; pp < 4; pp++) {
                uint32_t t[4];
                ldsm_x4(t, swz(bb, br + pp * 16, ks * 2 + bc));
                bfr[2 * pp][0] = t[0]; bfr[2 * pp][1] = t[1];
                bfr[2 * pp + 1][0] = t[2]; bfr[2 * pp + 1][1] = t[3];
            }
            #pragma unroll
            for (int mt = 0; mt < 4; mt++)
                #pragma unroll
                for (int nt = 0; nt < 8; nt++)
                    mma_bf16(acc[mt][nt], afr[mt], bfr[nt]);
        }
        __syncthreads();
        buf = (buf == NSTAGE - 1) ? 0 : buf + 1;
    }

    // epilogue: T row-major [b][m][4096], no guards (exact multiples)
    #pragma unroll
    for (int mt = 0; mt < 4; mt++) {
        int mrow = m0 + wm * 64 + mt * 16 + (lane >> 2);
        float* C0 = d_T + ((size_t)bI * SPA + mrow) * SPA;
        float* C1 = C0 + (size_t)8 * SPA;
        #pragma unroll
        for (int nt = 0; nt < 8; nt++) {
            int n = n0 + wn * 64 + nt * 8 + 2 * (lane & 3);
            *(float2*)&C0[n] = make_float2(acc[mt][nt][0], acc[mt][nt][1]);
            *(float2*)&C1[n] = make_float2(acc[mt][nt][2], acc[mt][nt][3]);
        }
    }
}

// ---------------------------------------------------------------------------
// 7) stage1: V[b][u][lx][ys][x] = sum_dx T[u, cl(2lx+dx-1), ys, cl(x+dx-1)]
//    grid (ys=64, u=64, b=4), block 256; smem = T[u, :, ys, :] (64x64)
// ---------------------------------------------------------------------------
__global__ void stage1_kernel() {
    __shared__ float sm[4096];
    int ys = blockIdx.x, u = blockIdx.y, b = blockIdx.z;
    int tid = threadIdx.x;
    const float* Trow = d_T + ((size_t)b * SPA + u * 64) * SPA + ys * 64;
    #pragma unroll
    for (int i = 0; i < 16; i++) {
        int idx = i * 256 + tid;
        int v = idx >> 6, xs = idx & 63;
        sm[idx] = Trow[(size_t)v * SPA + xs];
    }
    __syncthreads();
    float* Vb = d_V + (((size_t)(b * 64 + u) * 32) * 64 + ys) * 63;
    for (int o = tid; o < 32 * 63; o += 256) {
        int lx = o / 63, x = o - lx * 63;
        float s = 0.f;
        #pragma unroll
        for (int dx = 0; dx < 4; dx++)
            s += sm[clamp64(2 * lx + dx - 1) * 64 + clamp64(x + dx - 1)];
        Vb[(size_t)lx * (64 * 63) + x] = s;
    }
}

// ---------------------------------------------------------------------------
// 8) stage2: cos[b][ly*32+lx][y*63+x] = sum_dy V[cl(2ly+dy-1)][lx][cl(y+dy-1)][x]
//    grid (lx=32, ly=32, b=4), block 256, dyn smem 4 planes of 64x63
// ---------------------------------------------------------------------------
__global__ void stage2_kernel() {
    extern __shared__ float pl[];          // [4][4032]
    int lx = blockIdx.x, ly = blockIdx.y, b = blockIdx.z;
    int tid = threadIdx.x;
    #pragma unroll
    for (int dy = 0; dy < 4; dy++) {
        int u = clamp64(2 * ly + dy - 1);
        const float* Vp = d_V + (((size_t)(b * 64 + u) * 32 + lx) * 64) * 63;
        for (int idx = tid; idx < 4032; idx += 256)
            pl[dy * 4032 + idx] = Vp[idx];
    }
    __syncthreads();
    float* Crow = d_cos + ((size_t)(b * LL + ly * 32 + lx)) * CSTR;
    for (int o = tid; o < 63 * 63; o += 256) {
        int y = o / 63, x = o - y * 63;
        float s = 0.f;
        #pragma unroll
        for (int dy = 0; dy < 4; dy++)
            s += pl[dy * 4032 + clamp64(y + dy - 1) * 63 + x];
        Crow[o] = s;
    }
}

// ---------------------------------------------------------------------------
// 9) pass1: diag3 on flat (1024, 3969)
// ---------------------------------------------------------------------------
__global__ void pass1_kernel() {
    int q = blockIdx.x * 256 + threadIdx.x;
    if (q >= PP) return;
    int br = blockIdx.y;
    const float* base = d_cos + (size_t)(br >> 10) * LL * CSTR;
    int r = br & 1023;
    float s = base[(size_t)r * CSTR + q];
    if (r > 0 && q > 0)         s += base[(size_t)(r - 1) * CSTR + q - 1];
    if (r < 1023 && q < PP - 1) s += base[(size_t)(r + 1) * CSTR + q + 1];
    d_tmp[(size_t)br * CSTR + q] = s;
}

// ---------------------------------------------------------------------------
// 10) pass2: transposed-view diag3 + mask, back into d_cos
// ---------------------------------------------------------------------------
__global__ void pass2_kernel() {
    int q = blockIdx.x * 256 + threadIdx.x;
    if (q >= PP) return;
    int br = blockIdx.y;
    int b = br >> 10;
    int r = br & 1023;
    int ly = r >> 5, lx = r & 31;
    int r2 = lx * 32 + ly;
    int y = q / 63, x = q - 63 * y;
    int q2 = x * 63 + y;
    const float* tb = d_tmp + (size_t)b * LL * CSTR;
    float s = 0.f;
    #pragma unroll
    for (int d = -1; d <= 1; d++) {
        int rr = r2 + d, qq = q2 + d;
        if (rr >= 0 && rr < 1024 && qq >= 0 && qq < PP) {
            int lx2 = rr >> 5, ly2 = rr & 31;
            int x2 = qq / 63, y2 = qq - 63 * x2;
            s += tb[(size_t)(ly2 * 32 + lx2) * CSTR + (y2 * 63 + x2)];
        }
    }
    float mk = d_mmk[b * LL + r];
    float mp = d_mmp[b * PP + q];
    float mm = ((mk > mp && mp > 0.5f) || (mk == 1.0f)) ? 1.0f : 0.0f;
    d_cos[(size_t)br * CSTR + q] = s * mm;
}

// ---------------------------------------------------------------------------
// 11) softmax reduce over l
// ---------------------------------------------------------------------------
__global__ void smax_reduce_kernel() {
    int b  = blockIdx.y;
    int pl = threadIdx.x & 31;
    int lt = threadIdx.x >> 5;
    int p  = blockIdx.x * 32 + pl;
    float m = -1e30f, s = 0.f;
    if (p < PP) {
        const float* cf = d_cos + (size_t)b * LL * CSTR + p;
        for (int l = lt; l < LL; l += 8) {
            float x = 10.0f * cf[(size_t)l * CSTR];
            float mn = fmaxf(m, x);
            s = s * __expf(m - mn) + __expf(x - mn);
            m = mn;
        }
    }
    __shared__ float shm[8][32], shs[8][32];
    shm[lt][pl] = m;
    shs[lt][pl] = s;
    __syncthreads();
    if (lt == 0 && p < PP) {
        float M = shm[0][pl];
        #pragma unroll
        for (int t = 1; t < 8; t++) M = fmaxf(M, shm[t][pl]);
        float S = 0.f;
        #pragma unroll
        for (int t = 0; t < 8; t++) S += shs[t][pl] * __expf(shm[t][pl] - M);
        d_maxv[b * PP + p] = M;
        d_rcps[b * PP + p] = 1.0f / S;
    }
}

// ---------------------------------------------------------------------------
// 12) softmax write
// ---------------------------------------------------------------------------
__global__ void smax_write_kernel(float* __restrict__ out) {
    int q = blockIdx.x * 256 + threadIdx.x;
    if (q >= PP) return;
    int bl = blockIdx.y;
    int b = bl >> 10;
    float x = 10.0f * d_cos[(size_t)bl * CSTR + q];
    out[(size_t)bl * PP + q] = __expf(x - d_maxv[b * PP + q]) * d_rcps[b * PP + q];
}

// ---------------------------------------------------------------------------
extern "C" void kernel_launch(void* const* d_in, const int* in_sizes, int n_in,
                              void* d_out, int out_size) {
    const float* f    = (const float*)d_in[0];
    const float* bsrc = (const float*)d_in[1];
    const float* mask = (const float*)d_in[2];
    float* out = (float*)d_out;

    cudaFuncSetAttribute(gemm_T_kernel,
                         cudaFuncAttributeMaxDynamicSharedMemorySize, SM_BYTES);
    cudaFuncSetAttribute(stage2_kernel,
                         cudaFuncAttributeMaxDynamicSharedMemorySize, S2_SMEM);

    norm_kernel<<<NB * NC, 256>>>(bsrc);
    build_bn_split<<<(NB * SPA * NC) / 256, 256>>>(bsrc);
    build_f_split<<<(NB * SPA * NC) / 256, 256>>>(f);
    mmk_kernel<<<(NB * LL) / 256, 256>>>(mask);
    mmp_kernel<<<dim3((PP + 255) / 256, NB), 256>>>(mask);

    gemm_T_kernel<<<dim3(SPA / BN, SPA / BM, NB), 256, SM_BYTES>>>();

    stage1_kernel<<<dim3(64, 64, NB), 256>>>();
    stage2_kernel<<<dim3(32, 32, NB), 256, S2_SMEM>>>();

    dim3 g2((PP + 255) / 256, NB * LL);
    pass1_kernel<<<g2, 256>>>();
    pass2_kernel<<<g2, 256>>>();

    smax_reduce_kernel<<<dim3((PP + 31) / 32, NB), 256>>>();
    smax_write_kernel<<<g2, 256>>>(out);
}

// round 13
// speedup vs baseline: 1.3014x; 1.0681x over previous
#include <cuda_runtime.h>
#include <cuda_bf16.h>
#include <cstdint>

// Problem constants
// B=4, C=64, H=W=64, PS=4, PD=1, UFSTRIDE=2, STRIDE=1, SCALE=10
// Factorization: T[u,v,ys,xs] = sum_c bn[c,u,v] * f[c,ys,xs]   (GEMM, K=64, bf16 3-split)
//   cos[ly,lx,y,x] = sum_{dy,dx} T[cl(2ly+dy-1), cl(2lx+dx-1), cl(y+dy-1), cl(x+dx-1)]
// stage1 (dx sum) is FUSED into the GEMM epilogue: each warp's 64x64 acc subtile is
// exactly one (u, ys) plane of T; V is written directly, T never hits DRAM.

#define NB    4
#define NC    64
#define LL    1024
#define PP    3969
#define CSTR  3972
#define SPA   4096         // 64*64 spatial positions (GEMM M and N)
#define GKS   192          // 3-split K = 3*64
#define ROWB  384          // bytes per split row (192 bf16)

// GEMM tiling
#define BM    128
#define BN    256
#define NCHUNK 3
#define ABYTES (BM * 128)
#define BBYTES (BN * 128)
#define BUFBYTES (ABYTES + BBYTES)   // 49152
#define NSTAGE 3
#define SM_BYTES (NSTAGE * BUFBYTES) // 147456  (>= 8 * 64*66*4 = 135168 epilogue panes)
#define S2_SMEM (4 * 4032 * 4)       // stage2: 4 planes of 64x63 f32 = 64512

static __device__ float d_invn[NB * NC];
static __device__ __align__(16) __nv_bfloat16 d_A2[(size_t)NB * SPA * GKS];  // bn split [hi,hi,lo]
static __device__ __align__(16) __nv_bfloat16 d_F2[(size_t)NB * SPA * GKS];  // f  split [hi,lo,hi]
static __device__ float d_V  [(size_t)NB * 64 * 32 * 64 * 63];                // 132 MB
static __device__ float d_cos [(size_t)NB * LL * CSTR];
static __device__ float d_tmp [(size_t)NB * LL * CSTR];
static __device__ float d_mmk [NB * LL];
static __device__ float d_mmp [NB * PP];
static __device__ float d_maxv[NB * PP];
static __device__ float d_rcps[NB * PP];

__device__ __forceinline__ int clamp64(int v) { return min(max(v, 0), 63); }

__device__ __forceinline__ uint32_t smem_u32(const void* p) {
    uint32_t a;
    asm("{ .reg .u64 t; cvta.to.shared.u64 t, %1; cvt.u32.u64 %0, t; }" : "=r"(a) : "l"(p));
    return a;
}
__device__ __forceinline__ void cp_async16(uint32_t dst, const void* src) {
    asm volatile("cp.async.cg.shared.global [%0], [%1], 16;" :: "r"(dst), "l"(src) : "memory");
}
__device__ __forceinline__ void ldsm_x4(uint32_t* r, uint32_t addr) {
    asm volatile("ldmatrix.sync.aligned.m8n8.x4.shared.b16 {%0,%1,%2,%3}, [%4];"
                 : "=r"(r[0]), "=r"(r[1]), "=r"(r[2]), "=r"(r[3]) : "r"(addr));
}
__device__ __forceinline__ void mma_bf16(float* c, const uint32_t* a, const uint32_t* b) {
    asm volatile(
        "mma.sync.aligned.m16n8k16.row.col.f32.bf16.bf16.f32 "
        "{%0,%1,%2,%3}, {%4,%5,%6,%7}, {%8,%9}, {%0,%1,%2,%3};"
        : "+f"(c[0]), "+f"(c[1]), "+f"(c[2]), "+f"(c[3])
        : "r"(a[0]), "r"(a[1]), "r"(a[2]), "r"(a[3]), "r"(b[0]), "r"(b[1]));
}
__device__ __forceinline__ uint32_t swz(uint32_t base, int r, int c) {
    return base + r * 128 + ((c ^ (r & 7)) << 4);
}

// ---------------------------------------------------------------------------
// 1) per-(b,c) inverse L2 norm of b
// ---------------------------------------------------------------------------
__global__ void norm_kernel(const float* __restrict__ bsrc) {
    int bc = blockIdx.x;
    const float* src = bsrc + (size_t)bc * 4096;
    float s = 0.f;
    for (int i = threadIdx.x; i < 4096; i += 256) {
        float v = src[i];
        s += v * v;
    }
    __shared__ float sh[256];
    sh[threadIdx.x] = s;
    __syncthreads();
    for (int o = 128; o > 0; o >>= 1) {
        if (threadIdx.x < o) sh[threadIdx.x] += sh[threadIdx.x + o];
        __syncthreads();
    }
    if (threadIdx.x == 0) d_invn[bc] = 1.0f / sqrtf(sh[0] + 1e-8f);
}

// ---------------------------------------------------------------------------
// 2) build bn split A2[b][s=u*64+v][seg*64+c], segs [hi,hi,lo]
// ---------------------------------------------------------------------------
__global__ void build_bn_split(const float* __restrict__ bsrc) {
    int idx = blockIdx.x * 256 + threadIdx.x;     // NB*4096*64
    int c = idx & 63;
    int s = (idx >> 6) & 4095;
    int b = idx >> 18;
    float a = bsrc[((size_t)(b * NC + c)) * 4096 + s] * d_invn[b * NC + c];
    __nv_bfloat16 hi = __float2bfloat16(a);
    __nv_bfloat16 lo = __float2bfloat16(a - __bfloat162float(hi));
    size_t row = ((size_t)b * SPA + s) * GKS;
    d_A2[row + c]        = hi;
    d_A2[row + 64 + c]   = hi;
    d_A2[row + 128 + c]  = lo;
}

// ---------------------------------------------------------------------------
// 3) build f split F2[b][s][seg*64+c], segs [hi,lo,hi]
// ---------------------------------------------------------------------------
__global__ void build_f_split(const float* __restrict__ fsrc) {
    int idx = blockIdx.x * 256 + threadIdx.x;
    int c = idx & 63;
    int s = (idx >> 6) & 4095;
    int b = idx >> 18;
    float v = fsrc[((size_t)(b * NC + c)) * 4096 + s];
    __nv_bfloat16 hi = __float2bfloat16(v);
    __nv_bfloat16 lo = __float2bfloat16(v - __bfloat162float(hi));
    size_t row = ((size_t)b * SPA + s) * GKS;
    d_F2[row + c]        = hi;
    d_F2[row + 64 + c]   = lo;
    d_F2[row + 128 + c]  = hi;
}

// ---------------------------------------------------------------------------
// 4/5) mask means
// ---------------------------------------------------------------------------
__global__ void mmk_kernel(const float* __restrict__ mask) {
    int idx = blockIdx.x * 256 + threadIdx.x;
    int l = idx & 1023, b = idx >> 10;
    int ly = l >> 5, lx = l & 31;
    const float* m = mask + (size_t)b * 4096;
    float s = 0.f;
    #pragma unroll
    for (int i = 0; i < 4; i++)
        #pragma unroll
        for (int j = 0; j < 4; j++)
            s += 1.0f - m[clamp64(2 * ly + i - 1) * 64 + clamp64(2 * lx + j - 1)];
    d_mmk[idx] = s * 0.0625f;
}
__global__ void mmp_kernel(const float* __restrict__ mask) {
    int p = blockIdx.x * 256 + threadIdx.x;
    if (p >= PP) return;
    int b = blockIdx.y;
    int y = p / 63, x = p - 63 * y;
    const float* m = mask + (size_t)b * 4096;
    float s = 0.f;
    #pragma unroll
    for (int i = 0; i < 4; i++)
        #pragma unroll
        for (int j = 0; j < 4; j++)
            s += 1.0f - m[clamp64(y + i - 1) * 64 + clamp64(x + j - 1)];
    d_mmp[b * PP + p] = s * 0.0625f;
}

// ---------------------------------------------------------------------------
// 6) bf16 3-split GEMM + fused dx-stencil epilogue:
//    warp (wm,wn) computes T subtile [u = 2*by+wm][v 0..63][ys = 4*bx+wn][xs 0..63],
//    dumps it to a private smem pane, applies the 4-tap dx stencil, writes V.
// ---------------------------------------------------------------------------
__global__ void __launch_bounds__(256, 1)
gemm_V_kernel() {
    extern __shared__ char smem[];
    const uint32_t sb = smem_u32(smem);
    const int tid  = threadIdx.x;
    const int wid  = tid >> 5;
    const int lane = tid & 31;
    const int wm   = wid >> 2;
    const int wn   = wid & 3;
    const int bI = blockIdx.z;
    const int m0 = blockIdx.y * BM;
    const int n0 = blockIdx.x * BN;

    const char* Ag = (const char*)d_A2 + ((size_t)bI * SPA + m0) * ROWB;
    const char* Bg = (const char*)d_F2 + ((size_t)bI * SPA + n0) * ROWB;

    float acc[4][8][4];
    #pragma unroll
    for (int mt = 0; mt < 4; mt++)
        #pragma unroll
        for (int nt = 0; nt < 8; nt++)
            #pragma unroll
            for (int e = 0; e < 4; e++) acc[mt][nt][e] = 0.f;

    const int ar = wm * 64 + (lane & 15);
    const int ac = (lane >> 4);
    const int br = wn * 64 + (lane & 7) + ((lane >> 4) << 3);
    const int bc = (lane >> 3) & 1;

    auto load_chunk = [&](int ch, int buf) {
        const uint32_t ab = sb + buf * BUFBYTES;
        const uint32_t bb = ab + ABYTES;
        const size_t koff = (size_t)ch * 128;
        #pragma unroll
        for (int i = 0; i < 4; i++) {
            int idx = i * 256 + tid;
            int r = idx >> 3, c = idx & 7;
            cp_async16(swz(ab, r, c), Ag + (size_t)r * ROWB + koff + c * 16);
        }
        #pragma unroll
        for (int i = 0; i < 8; i++) {
            int idx = i * 256 + tid;
            int r = idx >> 3, c = idx & 7;
            cp_async16(swz(bb, r, c), Bg + (size_t)r * ROWB + koff + c * 16);
        }
        asm volatile("cp.async.commit_group;" ::: "memory");
    };

    load_chunk(0, 0);
    load_chunk(1, 1);
    load_chunk(2, 2);

    int buf = 0;
    for (int ch = 0; ch < NCHUNK; ch++) {
        if (ch < NCHUNK - 2)       asm volatile("cp.async.wait_group 2;" ::: "memory");
        else if (ch == NCHUNK - 2) asm volatile("cp.async.wait_group 1;" ::: "memory");
        else                       asm volatile("cp.async.wait_group 0;" ::: "memory");
        __syncthreads();

        const uint32_t ab = sb + buf * BUFBYTES;
        const uint32_t bb = ab + ABYTES;
        #pragma unroll
        for (int ks = 0; ks < 4; ks++) {
            uint32_t afr[4][4];
            #pragma unroll
            for (int mt = 0; mt < 4; mt++)
                ldsm_x4(afr[mt], swz(ab, ar + mt * 16, ks * 2 + ac));
            uint32_t bfr[8][2];
            #pragma unroll
            for (int pp = 0; pp < 4; pp++) {
                uint32_t t[4];
                ldsm_x4(t, swz(bb, br + pp * 16, ks * 2 + bc));
                bfr[2 * pp][0] = t[0]; bfr[2 * pp][1] = t[1];
                bfr[2 * pp + 1][0] = t[2]; bfr[2 * pp + 1][1] = t[3];
            }
            #pragma unroll
            for (int mt = 0; mt < 4; mt++)
                #pragma unroll
                for (int nt = 0; nt < 8; nt++)
                    mma_bf16(acc[mt][nt], afr[mt], bfr[nt]);
        }
        __syncthreads();
        buf = (buf == NSTAGE - 1) ? 0 : buf + 1;
    }
    // all MMAs done in all warps; smem buffers are free for epilogue panes
    __syncthreads();

    // ---- fused stage1 epilogue: acc (= T[u, v, ys, xs] subtile) -> smem pane ----
    float* W = (float*)smem + wid * (64 * 66);   // 64 rows (v) x 66 (xs padded)
    #pragma unroll
    for (int mt = 0; mt < 4; mt++) {
        int v0 = mt * 16 + (lane >> 2);
        #pragma unroll
        for (int nt = 0; nt < 8; nt++) {
            int xs = nt * 8 + 2 * (lane & 3);
            W[v0 * 66 + xs]           = acc[mt][nt][0];
            W[v0 * 66 + xs + 1]       = acc[mt][nt][1];
            W[(v0 + 8) * 66 + xs]     = acc[mt][nt][2];
            W[(v0 + 8) * 66 + xs + 1] = acc[mt][nt][3];
        }
    }
    __syncwarp();

    const int u  = (m0 >> 6) + wm;
    const int ys = (n0 >> 6) + wn;
    float* Vout = d_V + (((size_t)(bI * 64 + u) * 32) * 64 + ys) * 63;
    for (int o = lane; o < 32 * 63; o += 32) {
        int lx = o / 63, x = o - lx * 63;
        float s = 0.f;
        #pragma unroll
        for (int dx = 0; dx < 4; dx++)
            s += W[clamp64(2 * lx + dx - 1) * 66 + clamp64(x + dx - 1)];
        Vout[(size_t)lx * (64 * 63) + x] = s;
    }
}

// ---------------------------------------------------------------------------
// 7) stage2: cos[b][ly*32+lx][y*63+x] = sum_dy V[cl(2ly+dy-1)][lx][cl(y+dy-1)][x]
// ---------------------------------------------------------------------------
__global__ void stage2_kernel() {
    extern __shared__ float pl[];          // [4][4032]
    int lx = blockIdx.x, ly = blockIdx.y, b = blockIdx.z;
    int tid = threadIdx.x;
    #pragma unroll
    for (int dy = 0; dy < 4; dy++) {
        int u = clamp64(2 * ly + dy - 1);
        const float* Vp = d_V + (((size_t)(b * 64 + u) * 32 + lx) * 64) * 63;
        for (int idx = tid; idx < 4032; idx += 256)
            pl[dy * 4032 + idx] = Vp[idx];
    }
    __syncthreads();
    float* Crow = d_cos + ((size_t)(b * LL + ly * 32 + lx)) * CSTR;
    for (int o = tid; o < 63 * 63; o += 256) {
        int y = o / 63, x = o - y * 63;
        float s = 0.f;
        #pragma unroll
        for (int dy = 0; dy < 4; dy++)
            s += pl[dy * 4032 + clamp64(y + dy - 1) * 63 + x];
        Crow[o] = s;
    }
}

// ---------------------------------------------------------------------------
// 8) pass1: diag3 on flat (1024, 3969)
// ---------------------------------------------------------------------------
__global__ void pass1_kernel() {
    int q = blockIdx.x * 256 + threadIdx.x;
    if (q >= PP) return;
    int br = blockIdx.y;
    const float* base = d_cos + (size_t)(br >> 10) * LL * CSTR;
    int r = br & 1023;
    float s = base[(size_t)r * CSTR + q];
    if (r > 0 && q > 0)         s += base[(size_t)(r - 1) * CSTR + q - 1];
    if (r < 1023 && q < PP - 1) s += base[(size_t)(r + 1) * CSTR + q + 1];
    d_tmp[(size_t)br * CSTR + q] = s;
}

// ---------------------------------------------------------------------------
// 9) pass2: transposed-view diag3 + mask, back into d_cos
// ---------------------------------------------------------------------------
__global__ void pass2_kernel() {
    int q = blockIdx.x * 256 + threadIdx.x;
    if (q >= PP) return;
    int br = blockIdx.y;
    int b = br >> 10;
    int r = br & 1023;
    int ly = r >> 5, lx = r & 31;
    int r2 = lx * 32 + ly;
    int y = q / 63, x = q - 63 * y;
    int q2 = x * 63 + y;
    const float* tb = d_tmp + (size_t)b * LL * CSTR;
    float s = 0.f;
    #pragma unroll
    for (int d = -1; d <= 1; d++) {
        int rr = r2 + d, qq = q2 + d;
        if (rr >= 0 && rr < 1024 && qq >= 0 && qq < PP) {
            int lx2 = rr >> 5, ly2 = rr & 31;
            int x2 = qq / 63, y2 = qq - 63 * x2;
            s += tb[(size_t)(ly2 * 32 + lx2) * CSTR + (y2 * 63 + x2)];
        }
    }
    float mk = d_mmk[b * LL + r];
    float mp = d_mmp[b * PP + q];
    float mm = ((mk > mp && mp > 0.5f) || (mk == 1.0f)) ? 1.0f : 0.0f;
    d_cos[(size_t)br * CSTR + q] = s * mm;
}

// ---------------------------------------------------------------------------
// 10) softmax reduce over l
// ---------------------------------------------------------------------------
__global__ void smax_reduce_kernel() {
    int b  = blockIdx.y;
    int pl = threadIdx.x & 31;
    int lt = threadIdx.x >> 5;
    int p  = blockIdx.x * 32 + pl;
    float m = -1e30f, s = 0.f;
    if (p < PP) {
        const float* cf = d_cos + (size_t)b * LL * CSTR + p;
        for (int l = lt; l < LL; l += 8) {
            float x = 10.0f * cf[(size_t)l * CSTR];
            float mn = fmaxf(m, x);
            s = s * __expf(m - mn) + __expf(x - mn);
            m = mn;
        }
    }
    __shared__ float shm[8][32], shs[8][32];
    shm[lt][pl] = m;
    shs[lt][pl] = s;
    __syncthreads();
    if (lt == 0 && p < PP) {
        float M = shm[0][pl];
        #pragma unroll
        for (int t = 1; t < 8; t++) M = fmaxf(M, shm[t][pl]);
        float S = 0.f;
        #pragma unroll
        for (int t = 0; t < 8; t++) S += shs[t][pl] * __expf(shm[t][pl] - M);
        d_maxv[b * PP + p] = M;
        d_rcps[b * PP + p] = 1.0f / S;
    }
}

// ---------------------------------------------------------------------------
// 11) softmax write
// ---------------------------------------------------------------------------
__global__ void smax_write_kernel(float* __restrict__ out) {
    int q = blockIdx.x * 256 + threadIdx.x;
    if (q >= PP) return;
    int bl = blockIdx.y;
    int b = bl >> 10;
    float x = 10.0f * d_cos[(size_t)bl * CSTR + q];
    out[(size_t)bl * PP + q] = __expf(x - d_maxv[b * PP + q]) * d_rcps[b * PP + q];
}

// ---------------------------------------------------------------------------
extern "C" void kernel_launch(void* const* d_in, const int* in_sizes, int n_in,
                              void* d_out, int out_size) {
    const float* f    = (const float*)d_in[0];
    const float* bsrc = (const float*)d_in[1];
    const float* mask = (const float*)d_in[2];
    float* out = (float*)d_out;

    cudaFuncSetAttribute(gemm_V_kernel,
                         cudaFuncAttributeMaxDynamicSharedMemorySize, SM_BYTES);
    cudaFuncSetAttribute(stage2_kernel,
                         cudaFuncAttributeMaxDynamicSharedMemorySize, S2_SMEM);

    norm_kernel<<<NB * NC, 256>>>(bsrc);
    build_bn_split<<<(NB * SPA * NC) / 256, 256>>>(bsrc);
    build_f_split<<<(NB * SPA * NC) / 256, 256>>>(f);
    mmk_kernel<<<(NB * LL) / 256, 256>>>(mask);
    mmp_kernel<<<dim3((PP + 255) / 256, NB), 256>>>(mask);

    gemm_V_kernel<<<dim3(SPA / BN, SPA / BM, NB), 256, SM_BYTES>>>();

    stage2_kernel<<<dim3(32, 32, NB), 256, S2_SMEM>>>();

    dim3 g2((PP + 255) / 256, NB * LL);
    pass1_kernel<<<g2, 256>>>();
    pass2_kernel<<<g2, 256>>>();

    smax_reduce_kernel<<<dim3((PP + 31) / 32, NB), 256>>>();
    smax_write_kernel<<<g2, 256>>>(out);
}

// round 14
// speedup vs baseline: 1.4520x; 1.1157x over previous
#include <cuda_runtime.h>
#include <cuda_bf16.h>
#include <cstdint>

// Problem constants
// B=4, C=64, H=W=64, PS=4, PD=1, UFSTRIDE=2, STRIDE=1, SCALE=10
// Factorization: T[u,v,ys,xs] = sum_c bn[c,u,v] * f[c,ys,xs]   (GEMM, K=64, bf16 3-split)
//   cos[ly,lx,y,x] = sum_{dy,dx} T[cl(2ly+dy-1), cl(2lx+dx-1), cl(y+dy-1), cl(x+dx-1)]
// stage1 (dx) fused into GEMM epilogue; stage2 (dy) separate; fuse passes (diag3 x2)
// composed into ONE 9-tap kernel writing d_tmp; softmax reads d_tmp.

#define NB    4
#define NC    64
#define LL    1024
#define PP    3969
#define CSTR  3972
#define SPA   4096
#define GKS   192          // 3-split K = 3*64
#define ROWB  384          // bytes per split row

#define BM    128
#define BN    256
#define NCHUNK 3
#define ABYTES (BM * 128)
#define BBYTES (BN * 128)
#define BUFBYTES (ABYTES + BBYTES)   // 49152
#define NSTAGE 3
#define SM_BYTES (NSTAGE * BUFBYTES) // 147456 (>= 8*64*66*4 epilogue panes)
#define S2_SMEM (4 * 4032 * 4)       // 64512

static __device__ float d_invn[NB * NC];
static __device__ __align__(16) __nv_bfloat16 d_A2[(size_t)NB * SPA * GKS];
static __device__ __align__(16) __nv_bfloat16 d_F2[(size_t)NB * SPA * GKS];
static __device__ float d_V  [(size_t)NB * 64 * 32 * 64 * 63];
static __device__ float d_cos [(size_t)NB * LL * CSTR];   // raw fused-input cos (stage2 out)
static __device__ float d_tmp [(size_t)NB * LL * CSTR];   // masked fused cos (9-tap out)
static __device__ float d_mmk [NB * LL];
static __device__ float d_mmp [NB * PP];
static __device__ float d_maxv[NB * PP];
static __device__ float d_rcps[NB * PP];

__device__ __forceinline__ int clamp64(int v) { return min(max(v, 0), 63); }

__device__ __forceinline__ uint32_t smem_u32(const void* p) {
    uint32_t a;
    asm("{ .reg .u64 t; cvta.to.shared.u64 t, %1; cvt.u32.u64 %0, t; }" : "=r"(a) : "l"(p));
    return a;
}
__device__ __forceinline__ void cp_async16(uint32_t dst, const void* src) {
    asm volatile("cp.async.cg.shared.global [%0], [%1], 16;" :: "r"(dst), "l"(src) : "memory");
}
__device__ __forceinline__ void ldsm_x4(uint32_t* r, uint32_t addr) {
    asm volatile("ldmatrix.sync.aligned.m8n8.x4.shared.b16 {%0,%1,%2,%3}, [%4];"
                 : "=r"(r[0]), "=r"(r[1]), "=r"(r[2]), "=r"(r[3]) : "r"(addr));
}
__device__ __forceinline__ void mma_bf16(float* c, const uint32_t* a, const uint32_t* b) {
    asm volatile(
        "mma.sync.aligned.m16n8k16.row.col.f32.bf16.bf16.f32 "
        "{%0,%1,%2,%3}, {%4,%5,%6,%7}, {%8,%9}, {%0,%1,%2,%3};"
        : "+f"(c[0]), "+f"(c[1]), "+f"(c[2]), "+f"(c[3])
        : "r"(a[0]), "r"(a[1]), "r"(a[2]), "r"(a[3]), "r"(b[0]), "r"(b[1]));
}
__device__ __forceinline__ uint32_t swz(uint32_t base, int r, int c) {
    return base + r * 128 + ((c ^ (r & 7)) << 4);
}

// ---------------------------------------------------------------------------
// 1) per-(b,c) inverse L2 norm of b
// ---------------------------------------------------------------------------
__global__ void norm_kernel(const float* __restrict__ bsrc) {
    int bc = blockIdx.x;
    const float* src = bsrc + (size_t)bc * 4096;
    float s = 0.f;
    for (int i = threadIdx.x; i < 4096; i += 256) {
        float v = src[i];
        s += v * v;
    }
    __shared__ float sh[256];
    sh[threadIdx.x] = s;
    __syncthreads();
    for (int o = 128; o > 0; o >>= 1) {
        if (threadIdx.x < o) sh[threadIdx.x] += sh[threadIdx.x + o];
        __syncthreads();
    }
    if (threadIdx.x == 0) d_invn[bc] = 1.0f / sqrtf(sh[0] + 1e-8f);
}

// ---------------------------------------------------------------------------
// 2) build both bf16 splits: A2 (bn, [hi,hi,lo]) and F2 (f, [hi,lo,hi])
// ---------------------------------------------------------------------------
__global__ void build_AF_split(const float* __restrict__ bsrc,
                               const float* __restrict__ fsrc) {
    int idx = blockIdx.x * 256 + threadIdx.x;     // NB*4096*64
    int c = idx & 63;
    int s = (idx >> 6) & 4095;
    int b = idx >> 18;
    size_t row = ((size_t)b * SPA + s) * GKS;

    float a = bsrc[((size_t)(b * NC + c)) * 4096 + s] * d_invn[b * NC + c];
    __nv_bfloat16 ahi = __float2bfloat16(a);
    __nv_bfloat16 alo = __float2bfloat16(a - __bfloat162float(ahi));
    d_A2[row + c]       = ahi;
    d_A2[row + 64 + c]  = ahi;
    d_A2[row + 128 + c] = alo;

    float v = fsrc[((size_t)(b * NC + c)) * 4096 + s];
    __nv_bfloat16 fhi = __float2bfloat16(v);
    __nv_bfloat16 flo = __float2bfloat16(v - __bfloat162float(fhi));
    d_F2[row + c]       = fhi;
    d_F2[row + 64 + c]  = flo;
    d_F2[row + 128 + c] = fhi;
}

// ---------------------------------------------------------------------------
// 3) mask means, merged: every (b,p) does mmp; p<LL also does mmk
// ---------------------------------------------------------------------------
__global__ void masks_kernel(const float* __restrict__ mask) {
    int p = blockIdx.x * 256 + threadIdx.x;
    int b = blockIdx.y;
    const float* m = mask + (size_t)b * 4096;
    if (p < PP) {
        int y = p / 63, x = p - 63 * y;
        float s = 0.f;
        #pragma unroll
        for (int i = 0; i < 4; i++)
            #pragma unroll
            for (int j = 0; j < 4; j++)
                s += 1.0f - m[clamp64(y + i - 1) * 64 + clamp64(x + j - 1)];
        d_mmp[b * PP + p] = s * 0.0625f;
    }
    if (p < LL) {
        int ly = p >> 5, lx = p & 31;
        float s = 0.f;
        #pragma unroll
        for (int i = 0; i < 4; i++)
            #pragma unroll
            for (int j = 0; j < 4; j++)
                s += 1.0f - m[clamp64(2 * ly + i - 1) * 64 + clamp64(2 * lx + j - 1)];
        d_mmk[b * LL + p] = s * 0.0625f;
    }
}

// ---------------------------------------------------------------------------
// 4) bf16 3-split GEMM + fused dx-stencil epilogue -> V
// ---------------------------------------------------------------------------
__global__ void __launch_bounds__(256, 1)
gemm_V_kernel() {
    extern __shared__ char smem[];
    const uint32_t sb = smem_u32(smem);
    const int tid  = threadIdx.x;
    const int wid  = tid >> 5;
    const int lane = tid & 31;
    const int wm   = wid >> 2;
    const int wn   = wid & 3;
    const int bI = blockIdx.z;
    const int m0 = blockIdx.y * BM;
    const int n0 = blockIdx.x * BN;

    const char* Ag = (const char*)d_A2 + ((size_t)bI * SPA + m0) * ROWB;
    const char* Bg = (const char*)d_F2 + ((size_t)bI * SPA + n0) * ROWB;

    float acc[4][8][4];
    #pragma unroll
    for (int mt = 0; mt < 4; mt++)
        #pragma unroll
        for (int nt = 0; nt < 8; nt++)
            #pragma unroll
            for (int e = 0; e < 4; e++) acc[mt][nt][e] = 0.f;

    const int ar = wm * 64 + (lane & 15);
    const int ac = (lane >> 4);
    const int br = wn * 64 + (lane & 7) + ((lane >> 4) << 3);
    const int bc = (lane >> 3) & 1;

    auto load_chunk = [&](int ch, int buf) {
        const uint32_t ab = sb + buf * BUFBYTES;
        const uint32_t bb = ab + ABYTES;
        const size_t koff = (size_t)ch * 128;
        #pragma unroll
        for (int i = 0; i < 4; i++) {
            int idx = i * 256 + tid;
            int r = idx >> 3, c = idx & 7;
            cp_async16(swz(ab, r, c), Ag + (size_t)r * ROWB + koff + c * 16);
        }
        #pragma unroll
        for (int i = 0; i < 8; i++) {
            int idx = i * 256 + tid;
            int r = idx >> 3, c = idx & 7;
            cp_async16(swz(bb, r, c), Bg + (size_t)r * ROWB + koff + c * 16);
        }
        asm volatile("cp.async.commit_group;" ::: "memory");
    };

    load_chunk(0, 0);
    load_chunk(1, 1);
    load_chunk(2, 2);

    int buf = 0;
    for (int ch = 0; ch < NCHUNK; ch++) {
        if (ch < NCHUNK - 2)       asm volatile("cp.async.wait_group 2;" ::: "memory");
        else if (ch == NCHUNK - 2) asm volatile("cp.async.wait_group 1;" ::: "memory");
        else                       asm volatile("cp.async.wait_group 0;" ::: "memory");
        __syncthreads();

        const uint32_t ab = sb + buf * BUFBYTES;
        const uint32_t bb = ab + ABYTES;
        #pragma unroll
        for (int ks = 0; ks < 4; ks++) {
            uint32_t afr[4][4];
            #pragma unroll
            for (int mt = 0; mt < 4; mt++)
                ldsm_x4(afr[mt], swz(ab, ar + mt * 16, ks * 2 + ac));
            uint32_t bfr[8][2];
            #pragma unroll
            for (int pp = 0; pp < 4; pp++) {
                uint32_t t[4];
                ldsm_x4(t, swz(bb, br + pp * 16, ks * 2 + bc));
                bfr[2 * pp][0] = t[0]; bfr[2 * pp][1] = t[1];
                bfr[2 * pp + 1][0] = t[2]; bfr[2 * pp + 1][1] = t[3];
            }
            #pragma unroll
            for (int mt = 0; mt < 4; mt++)
                #pragma unroll
                for (int nt = 0; nt < 8; nt++)
                    mma_bf16(acc[mt][nt], afr[mt], bfr[nt]);
        }
        __syncthreads();
        buf = (buf == NSTAGE - 1) ? 0 : buf + 1;
    }
    __syncthreads();

    // fused stage1 epilogue: acc (= T[u, v, ys, xs] subtile) -> smem pane -> V
    float* W = (float*)smem + wid * (64 * 66);
    #pragma unroll
    for (int mt = 0; mt < 4; mt++) {
        int v0 = mt * 16 + (lane >> 2);
        #pragma unroll
        for (int nt = 0; nt < 8; nt++) {
            int xs = nt * 8 + 2 * (lane & 3);
            W[v0 * 66 + xs]           = acc[mt][nt][0];
            W[v0 * 66 + xs + 1]       = acc[mt][nt][1];
            W[(v0 + 8) * 66 + xs]     = acc[mt][nt][2];
            W[(v0 + 8) * 66 + xs + 1] = acc[mt][nt][3];
        }
    }
    __syncwarp();

    const int u  = (m0 >> 6) + wm;
    const int ys = (n0 >> 6) + wn;
    float* Vout = d_V + (((size_t)(bI * 64 + u) * 32) * 64 + ys) * 63;
    for (int o = lane; o < 32 * 63; o += 32) {
        int lx = o / 63, x = o - lx * 63;
        float s = 0.f;
        #pragma unroll
        for (int dx = 0; dx < 4; dx++)
            s += W[clamp64(2 * lx + dx - 1) * 66 + clamp64(x + dx - 1)];
        Vout[(size_t)lx * (64 * 63) + x] = s;
    }
}

// ---------------------------------------------------------------------------
// 5) stage2: cos[b][ly*32+lx][y*63+x] = sum_dy V[cl(2ly+dy-1)][lx][cl(y+dy-1)][x]
// ---------------------------------------------------------------------------
__global__ void stage2_kernel() {
    extern __shared__ float pl[];          // [4][4032]
    int lx = blockIdx.x, ly = blockIdx.y, b = blockIdx.z;
    int tid = threadIdx.x;
    #pragma unroll
    for (int dy = 0; dy < 4; dy++) {
        int u = clamp64(2 * ly + dy - 1);
        const float* Vp = d_V + (((size_t)(b * 64 + u) * 32 + lx) * 64) * 63;
        for (int idx = tid; idx < 4032; idx += 256)
            pl[dy * 4032 + idx] = Vp[idx];
    }
    __syncthreads();
    float* Crow = d_cos + ((size_t)(b * LL + ly * 32 + lx)) * CSTR;
    for (int o = tid; o < 63 * 63; o += 256) {
        int y = o / 63, x = o - y * 63;
        float s = 0.f;
        #pragma unroll
        for (int dy = 0; dy < 4; dy++)
            s += pl[dy * 4032 + clamp64(y + dy - 1) * 63 + x];
        Crow[o] = s;
    }
}

// ---------------------------------------------------------------------------
// 6) fused 9-tap pass (pass2 ∘ pass1) + mask, d_cos -> d_tmp
// ---------------------------------------------------------------------------
__global__ void fused_pass_kernel() {
    int q = blockIdx.x * 256 + threadIdx.x;
    if (q >= PP) return;
    int br = blockIdx.y;
    int b = br >> 10;
    int r = br & 1023;
    int ly = r >> 5, lx = r & 31;
    int r2 = lx * 32 + ly;
    int y = q / 63, x = q - 63 * y;
    int q2 = x * 63 + y;
    const float* cb = d_cos + (size_t)b * LL * CSTR;
    float s = 0.f;
    #pragma unroll
    for (int d2 = -1; d2 <= 1; d2++) {
        int rr = r2 + d2, qq = q2 + d2;
        if (rr >= 0 && rr < 1024 && qq >= 0 && qq < PP) {
            int lx2 = rr >> 5, ly2 = rr & 31;
            int rf = ly2 * 32 + lx2;
            int x2 = qq / 63, y2 = qq - 63 * x2;
            int cf = y2 * 63 + x2;
            s += cb[(size_t)rf * CSTR + cf];
            if (rf > 0 && cf > 0)           s += cb[(size_t)(rf - 1) * CSTR + cf - 1];
            if (rf < 1023 && cf < PP - 1)   s += cb[(size_t)(rf + 1) * CSTR + cf + 1];
        }
    }
    float mk = d_mmk[b * LL + r];
    float mp = d_mmp[b * PP + q];
    float mm = ((mk > mp && mp > 0.5f) || (mk == 1.0f)) ? 1.0f : 0.0f;
    d_tmp[(size_t)br * CSTR + q] = s * mm;
}

// ---------------------------------------------------------------------------
// 7) softmax reduce over l (reads d_tmp)
// ---------------------------------------------------------------------------
__global__ void smax_reduce_kernel() {
    int b  = blockIdx.y;
    int pl = threadIdx.x & 31;
    int lt = threadIdx.x >> 5;
    int p  = blockIdx.x * 32 + pl;
    float m = -1e30f, s = 0.f;
    if (p < PP) {
        const float* cf = d_tmp + (size_t)b * LL * CSTR + p;
        for (int l = lt; l < LL; l += 8) {
            float x = 10.0f * cf[(size_t)l * CSTR];
            float mn = fmaxf(m, x);
            s = s * __expf(m - mn) + __expf(x - mn);
            m = mn;
        }
    }
    __shared__ float shm[8][32], shs[8][32];
    shm[lt][pl] = m;
    shs[lt][pl] = s;
    __syncthreads();
    if (lt == 0 && p < PP) {
        float M = shm[0][pl];
        #pragma unroll
        for (int t = 1; t < 8; t++) M = fmaxf(M, shm[t][pl]);
        float S = 0.f;
        #pragma unroll
        for (int t = 0; t < 8; t++) S += shs[t][pl] * __expf(shm[t][pl] - M);
        d_maxv[b * PP + p] = M;
        d_rcps[b * PP + p] = 1.0f / S;
    }
}

// ---------------------------------------------------------------------------
// 8) softmax write (reads d_tmp)
// ---------------------------------------------------------------------------
__global__ void smax_write_kernel(float* __restrict__ out) {
    int q = blockIdx.x * 256 + threadIdx.x;
    if (q >= PP) return;
    int bl = blockIdx.y;
    int b = bl >> 10;
    float x = 10.0f * d_tmp[(size_t)bl * CSTR + q];
    out[(size_t)bl * PP + q] = __expf(x - d_maxv[b * PP + q]) * d_rcps[b * PP + q];
}

// ---------------------------------------------------------------------------
extern "C" void kernel_launch(void* const* d_in, const int* in_sizes, int n_in,
                              void* d_out, int out_size) {
    const float* f    = (const float*)d_in[0];
    const float* bsrc = (const float*)d_in[1];
    const float* mask = (const float*)d_in[2];
    float* out = (float*)d_out;

    cudaFuncSetAttribute(gemm_V_kernel,
                         cudaFuncAttributeMaxDynamicSharedMemorySize, SM_BYTES);
    cudaFuncSetAttribute(stage2_kernel,
                         cudaFuncAttributeMaxDynamicSharedMemorySize, S2_SMEM);

    norm_kernel<<<NB * NC, 256>>>(bsrc);
    build_AF_split<<<(NB * SPA * NC) / 256, 256>>>(bsrc, f);
    masks_kernel<<<dim3((PP + 255) / 256, NB), 256>>>(mask);

    gemm_V_kernel<<<dim3(SPA / BN, SPA / BM, NB), 256, SM_BYTES>>>();

    stage2_kernel<<<dim3(32, 32, NB), 256, S2_SMEM>>>();

    dim3 g2((PP + 255) / 256, NB * LL);
    fused_pass_kernel<<<g2, 256>>>();

    smax_reduce_kernel<<<dim3((PP + 31) / 32, NB), 256>>>();
    smax_write_kernel<<<g2, 256>>>(out);
}

// round 15
// speedup vs baseline: 1.6074x; 1.1070x over previous
#include <cuda_runtime.h>
#include <cuda_bf16.h>
#include <cstdint>

// Problem constants
// B=4, C=64, H=W=64, PS=4, PD=1, UFSTRIDE=2, STRIDE=1, SCALE=10
// Factorization: T[u,v,ys,xs] = sum_c bn[c,u,v] * f[c,ys,xs]   (GEMM, K=64, bf16 3-split)
//   cos[ly,lx,y,x] = sum_{dy,dx} T[cl(2ly+dy-1), cl(2lx+dx-1), cl(y+dy-1), cl(x+dx-1)]
// stage1 (dx) fused into GEMM epilogue (strength-reduced); stage2 (dy) separate;
// fuse passes composed into one 9-tap kernel; softmax is max-free (overflow-safe).

#define NB    4
#define NC    64
#define LL    1024
#define PP    3969
#define CSTR  3972
#define SPA   4096
#define GKS   192          // 3-split K = 3*64
#define ROWB  384          // bytes per split row

#define BM    128
#define BN    256
#define NCHUNK 3
#define ABYTES (BM * 128)
#define BBYTES (BN * 128)
#define BUFBYTES (ABYTES + BBYTES)   // 49152
#define NSTAGE 3
#define SM_BYTES (NSTAGE * BUFBYTES) // 147456 (>= 8*64*66*4 epilogue panes)
#define S2_SMEM (4 * 4032 * 4)       // 64512

static __device__ float d_invn[NB * NC];
static __device__ __align__(16) __nv_bfloat16 d_A2[(size_t)NB * SPA * GKS];
static __device__ __align__(16) __nv_bfloat16 d_F2[(size_t)NB * SPA * GKS];
static __device__ float d_V  [(size_t)NB * 64 * 32 * 64 * 63];
static __device__ float d_cos [(size_t)NB * LL * CSTR];   // raw fused-input cos (stage2 out)
static __device__ float d_tmp [(size_t)NB * LL * CSTR];   // masked fused cos (9-tap out)
static __device__ float d_mmk [NB * LL];
static __device__ float d_mmp [NB * PP];
static __device__ float d_rcps[NB * PP];

__device__ __forceinline__ int clamp64(int v) { return min(max(v, 0), 63); }

__device__ __forceinline__ uint32_t smem_u32(const void* p) {
    uint32_t a;
    asm("{ .reg .u64 t; cvta.to.shared.u64 t, %1; cvt.u32.u64 %0, t; }" : "=r"(a) : "l"(p));
    return a;
}
__device__ __forceinline__ void cp_async16(uint32_t dst, const void* src) {
    asm volatile("cp.async.cg.shared.global [%0], [%1], 16;" :: "r"(dst), "l"(src) : "memory");
}
__device__ __forceinline__ void ldsm_x4(uint32_t* r, uint32_t addr) {
    asm volatile("ldmatrix.sync.aligned.m8n8.x4.shared.b16 {%0,%1,%2,%3}, [%4];"
                 : "=r"(r[0]), "=r"(r[1]), "=r"(r[2]), "=r"(r[3]) : "r"(addr));
}
__device__ __forceinline__ void mma_bf16(float* c, const uint32_t* a, const uint32_t* b) {
    asm volatile(
        "mma.sync.aligned.m16n8k16.row.col.f32.bf16.bf16.f32 "
        "{%0,%1,%2,%3}, {%4,%5,%6,%7}, {%8,%9}, {%0,%1,%2,%3};"
        : "+f"(c[0]), "+f"(c[1]), "+f"(c[2]), "+f"(c[3])
        : "r"(a[0]), "r"(a[1]), "r"(a[2]), "r"(a[3]), "r"(b[0]), "r"(b[1]));
}
__device__ __forceinline__ uint32_t swz(uint32_t base, int r, int c) {
    return base + r * 128 + ((c ^ (r & 7)) << 4);
}

// ---------------------------------------------------------------------------
// 1) per-(b,c) inverse L2 norm of b
// ---------------------------------------------------------------------------
__global__ void norm_kernel(const float* __restrict__ bsrc) {
    int bc = blockIdx.x;
    const float* src = bsrc + (size_t)bc * 4096;
    float s = 0.f;
    for (int i = threadIdx.x; i < 4096; i += 256) {
        float v = src[i];
        s += v * v;
    }
    __shared__ float sh[256];
    sh[threadIdx.x] = s;
    __syncthreads();
    for (int o = 128; o > 0; o >>= 1) {
        if (threadIdx.x < o) sh[threadIdx.x] += sh[threadIdx.x + o];
        __syncthreads();
    }
    if (threadIdx.x == 0) d_invn[bc] = 1.0f / sqrtf(sh[0] + 1e-8f);
}

// ---------------------------------------------------------------------------
// 2) build both bf16 splits: A2 (bn, [hi,hi,lo]) and F2 (f, [hi,lo,hi])
// ---------------------------------------------------------------------------
__global__ void build_AF_split(const float* __restrict__ bsrc,
                               const float* __restrict__ fsrc) {
    int idx = blockIdx.x * 256 + threadIdx.x;     // NB*4096*64
    int c = idx & 63;
    int s = (idx >> 6) & 4095;
    int b = idx >> 18;
    size_t row = ((size_t)b * SPA + s) * GKS;

    float a = bsrc[((size_t)(b * NC + c)) * 4096 + s] * d_invn[b * NC + c];
    __nv_bfloat16 ahi = __float2bfloat16(a);
    __nv_bfloat16 alo = __float2bfloat16(a - __bfloat162float(ahi));
    d_A2[row + c]       = ahi;
    d_A2[row + 64 + c]  = ahi;
    d_A2[row + 128 + c] = alo;

    float v = fsrc[((size_t)(b * NC + c)) * 4096 + s];
    __nv_bfloat16 fhi = __float2bfloat16(v);
    __nv_bfloat16 flo = __float2bfloat16(v - __bfloat162float(fhi));
    d_F2[row + c]       = fhi;
    d_F2[row + 64 + c]  = flo;
    d_F2[row + 128 + c] = fhi;
}

// ---------------------------------------------------------------------------
// 3) mask means, merged
// ---------------------------------------------------------------------------
__global__ void masks_kernel(const float* __restrict__ mask) {
    int p = blockIdx.x * 256 + threadIdx.x;
    int b = blockIdx.y;
    const float* m = mask + (size_t)b * 4096;
    if (p < PP) {
        int y = p / 63, x = p - 63 * y;
        float s = 0.f;
        #pragma unroll
        for (int i = 0; i < 4; i++)
            #pragma unroll
            for (int j = 0; j < 4; j++)
                s += 1.0f - m[clamp64(y + i - 1) * 64 + clamp64(x + j - 1)];
        d_mmp[b * PP + p] = s * 0.0625f;
    }
    if (p < LL) {
        int ly = p >> 5, lx = p & 31;
        float s = 0.f;
        #pragma unroll
        for (int i = 0; i < 4; i++)
            #pragma unroll
            for (int j = 0; j < 4; j++)
                s += 1.0f - m[clamp64(2 * ly + i - 1) * 64 + clamp64(2 * lx + j - 1)];
        d_mmk[b * LL + p] = s * 0.0625f;
    }
}

// ---------------------------------------------------------------------------
// 4) bf16 3-split GEMM + fused dx-stencil epilogue -> V (strength-reduced)
// ---------------------------------------------------------------------------
__global__ void __launch_bounds__(256, 1)
gemm_V_kernel() {
    extern __shared__ char smem[];
    const uint32_t sb = smem_u32(smem);
    const int tid  = threadIdx.x;
    const int wid  = tid >> 5;
    const int lane = tid & 31;
    const int wm   = wid >> 2;
    const int wn   = wid & 3;
    const int bI = blockIdx.z;
    const int m0 = blockIdx.y * BM;
    const int n0 = blockIdx.x * BN;

    const char* Ag = (const char*)d_A2 + ((size_t)bI * SPA + m0) * ROWB;
    const char* Bg = (const char*)d_F2 + ((size_t)bI * SPA + n0) * ROWB;

    float acc[4][8][4];
    #pragma unroll
    for (int mt = 0; mt < 4; mt++)
        #pragma unroll
        for (int nt = 0; nt < 8; nt++)
            #pragma unroll
            for (int e = 0; e < 4; e++) acc[mt][nt][e] = 0.f;

    const int ar = wm * 64 + (lane & 15);
    const int ac = (lane >> 4);
    const int br = wn * 64 + (lane & 7) + ((lane >> 4) << 3);
    const int bc = (lane >> 3) & 1;

    auto load_chunk = [&](int ch, int buf) {
        const uint32_t ab = sb + buf * BUFBYTES;
        const uint32_t bb = ab + ABYTES;
        const size_t koff = (size_t)ch * 128;
        #pragma unroll
        for (int i = 0; i < 4; i++) {
            int idx = i * 256 + tid;
            int r = idx >> 3, c = idx & 7;
            cp_async16(swz(ab, r, c), Ag + (size_t)r * ROWB + koff + c * 16);
        }
        #pragma unroll
        for (int i = 0; i < 8; i++) {
            int idx = i * 256 + tid;
            int r = idx >> 3, c = idx & 7;
            cp_async16(swz(bb, r, c), Bg + (size_t)r * ROWB + koff + c * 16);
        }
        asm volatile("cp.async.commit_group;" ::: "memory");
    };

    load_chunk(0, 0);
    load_chunk(1, 1);
    load_chunk(2, 2);

    int buf = 0;
    for (int ch = 0; ch < NCHUNK; ch++) {
        if (ch < NCHUNK - 2)       asm volatile("cp.async.wait_group 2;" ::: "memory");
        else if (ch == NCHUNK - 2) asm volatile("cp.async.wait_group 1;" ::: "memory");
        else                       asm volatile("cp.async.wait_group 0;" ::: "memory");
        __syncthreads();

        const uint32_t ab = sb + buf * BUFBYTES;
        const uint32_t bb = ab + ABYTES;
        #pragma unroll
        for (int ks = 0; ks < 4; ks++) {
            uint32_t afr[4][4];
            #pragma unroll
            for (int mt = 0; mt < 4; mt++)
                ldsm_x4(afr[mt], swz(ab, ar + mt * 16, ks * 2 + ac));
            uint32_t bfr[8][2];
            #pragma unroll
            for (int pp = 0; pp < 4; pp++) {
                uint32_t t[4];
                ldsm_x4(t, swz(bb, br + pp * 16, ks * 2 + bc));
                bfr[2 * pp][0] = t[0]; bfr[2 * pp][1] = t[1];
                bfr[2 * pp + 1][0] = t[2]; bfr[2 * pp + 1][1] = t[3];
            }
            #pragma unroll
            for (int mt = 0; mt < 4; mt++)
                #pragma unroll
                for (int nt = 0; nt < 8; nt++)
                    mma_bf16(acc[mt][nt], afr[mt], bfr[nt]);
        }
        __syncthreads();
        buf = (buf == NSTAGE - 1) ? 0 : buf + 1;
    }
    __syncthreads();

    // fused stage1 epilogue: acc (= T[u, v, ys, xs] subtile) -> smem pane -> V
    float* W = (float*)smem + wid * (64 * 66);
    #pragma unroll
    for (int mt = 0; mt < 4; mt++) {
        int v0 = mt * 16 + (lane >> 2);
        #pragma unroll
        for (int nt = 0; nt < 8; nt++) {
            int xs = nt * 8 + 2 * (lane & 3);
            *(float2*)&W[v0 * 66 + xs]       = make_float2(acc[mt][nt][0], acc[mt][nt][1]);
            *(float2*)&W[(v0 + 8) * 66 + xs] = make_float2(acc[mt][nt][2], acc[mt][nt][3]);
        }
    }
    __syncwarp();

    const int u  = (m0 >> 6) + wm;
    const int ys = (n0 >> 6) + wn;
    float* Vout = d_V + (((size_t)(bI * 64 + u) * 32) * 64 + ys) * 63;
    const int xA = lane;                // 0..31
    const int xB = lane + 32;           // 32..62 (lane < 31)
    #pragma unroll 4
    for (int lx = 0; lx < 32; lx++) {
        const float* r0 = W + clamp64(2 * lx - 1) * 66;
        const float* r1 = W + (2 * lx) * 66;
        const float* r2 = W + (2 * lx + 1) * 66;
        const float* r3 = W + clamp64(2 * lx + 2) * 66;
        float* vrow = Vout + (size_t)lx * 4032;
        float sA = r0[max(xA - 1, 0)] + r1[xA] + r2[xA + 1] + r3[min(xA + 2, 63)];
        vrow[xA] = sA;
        if (lane < 31) {
            float sB = r0[xB - 1] + r1[xB] + r2[xB + 1] + r3[min(xB + 2, 63)];
            vrow[xB] = sB;
        }
    }
}

// ---------------------------------------------------------------------------
// 5) stage2: cos[b][ly*32+lx][y*63+x] = sum_dy V[cl(2ly+dy-1)][lx][cl(y+dy-1)][x]
// ---------------------------------------------------------------------------
__global__ void stage2_kernel() {
    extern __shared__ float pl[];          // [4][4032]
    int lx = blockIdx.x, ly = blockIdx.y, b = blockIdx.z;
    int tid = threadIdx.x;
    #pragma unroll
    for (int dy = 0; dy < 4; dy++) {
        int u = clamp64(2 * ly + dy - 1);
        const float* Vp = d_V + (((size_t)(b * 64 + u) * 32 + lx) * 64) * 63;
        for (int idx = tid; idx < 4032; idx += 256)
            pl[dy * 4032 + idx] = Vp[idx];
    }
    __syncthreads();
    float* Crow = d_cos + ((size_t)(b * LL + ly * 32 + lx)) * CSTR;
    for (int o = tid; o < 63 * 63; o += 256) {
        int y = o / 63, x = o - y * 63;
        float s = 0.f;
        #pragma unroll
        for (int dy = 0; dy < 4; dy++)
            s += pl[dy * 4032 + clamp64(y + dy - 1) * 63 + x];
        Crow[o] = s;
    }
}

// ---------------------------------------------------------------------------
// 6) fused 9-tap pass (pass2 ∘ pass1) + mask, d_cos -> d_tmp
// ---------------------------------------------------------------------------
__global__ void fused_pass_kernel() {
    int q = blockIdx.x * 256 + threadIdx.x;
    if (q >= PP) return;
    int br = blockIdx.y;
    int b = br >> 10;
    int r = br & 1023;
    int ly = r >> 5, lx = r & 31;
    int r2 = lx * 32 + ly;
    int y = q / 63, x = q - 63 * y;
    int q2 = x * 63 + y;
    const float* cb = d_cos + (size_t)b * LL * CSTR;
    float s = 0.f;
    #pragma unroll
    for (int d2 = -1; d2 <= 1; d2++) {
        int rr = r2 + d2, qq = q2 + d2;
        if (rr >= 0 && rr < 1024 && qq >= 0 && qq < PP) {
            int lx2 = rr >> 5, ly2 = rr & 31;
            int rf = ly2 * 32 + lx2;
            int x2 = qq / 63, y2 = qq - 63 * x2;
            int cf = y2 * 63 + x2;
            s += cb[(size_t)rf * CSTR + cf];
            if (rf > 0 && cf > 0)           s += cb[(size_t)(rf - 1) * CSTR + cf - 1];
            if (rf < 1023 && cf < PP - 1)   s += cb[(size_t)(rf + 1) * CSTR + cf + 1];
        }
    }
    float mk = d_mmk[b * LL + r];
    float mp = d_mmp[b * PP + q];
    float mm = ((mk > mp && mp > 0.5f) || (mk == 1.0f)) ? 1.0f : 0.0f;
    d_tmp[(size_t)br * CSTR + q] = s * mm;
}

// ---------------------------------------------------------------------------
// 7) softmax sum (max-free; logits are 10*cosF, |logit| << 88 so exp is safe,
//    and masked entries contribute e^0=1 so the sum cannot underflow)
// ---------------------------------------------------------------------------
__global__ void smax_sum_kernel() {
    int b  = blockIdx.y;
    int pl = threadIdx.x & 31;
    int lt = threadIdx.x >> 5;
    int p  = blockIdx.x * 32 + pl;
    float s = 0.f;
    if (p < PP) {
        const float* cf = d_tmp + (size_t)b * LL * CSTR + p;
        for (int l = lt; l < LL; l += 8)
            s += __expf(10.0f * cf[(size_t)l * CSTR]);
    }
    __shared__ float shs[8][32];
    shs[lt][pl] = s;
    __syncthreads();
    if (lt == 0 && p < PP) {
        float S = 0.f;
        #pragma unroll
        for (int t = 0; t < 8; t++) S += shs[t][pl];
        d_rcps[b * PP + p] = 1.0f / S;
    }
}

// ---------------------------------------------------------------------------
// 8) softmax write
// ---------------------------------------------------------------------------
__global__ void smax_write_kernel(float* __restrict__ out) {
    int q = blockIdx.x * 256 + threadIdx.x;
    if (q >= PP) return;
    int bl = blockIdx.y;
    int b = bl >> 10;
    float x = 10.0f * d_tmp[(size_t)bl * CSTR + q];
    out[(size_t)bl * PP + q] = __expf(x) * d_rcps[b * PP + q];
}

// ---------------------------------------------------------------------------
extern "C" void kernel_launch(void* const* d_in, const int* in_sizes, int n_in,
                              void* d_out, int out_size) {
    const float* f    = (const float*)d_in[0];
    const float* bsrc = (const float*)d_in[1];
    const float* mask = (const float*)d_in[2];
    float* out = (float*)d_out;

    cudaFuncSetAttribute(gemm_V_kernel,
                         cudaFuncAttributeMaxDynamicSharedMemorySize, SM_BYTES);
    cudaFuncSetAttribute(stage2_kernel,
                         cudaFuncAttributeMaxDynamicSharedMemorySize, S2_SMEM);

    norm_kernel<<<NB * NC, 256>>>(bsrc);
    build_AF_split<<<(NB * SPA * NC) / 256, 256>>>(bsrc, f);
    masks_kernel<<<dim3((PP + 255) / 256, NB), 256>>>(mask);

    gemm_V_kernel<<<dim3(SPA / BN, SPA / BM, NB), 256, SM_BYTES>>>();

    stage2_kernel<<<dim3(32, 32, NB), 256, S2_SMEM>>>();

    dim3 g2((PP + 255) / 256, NB * LL);
    fused_pass_kernel<<<g2, 256>>>();

    smax_sum_kernel<<<dim3((PP + 31) / 32, NB), 256>>>();
    smax_write_kernel<<<g2, 256>>>(out);
}

// round 16
// speedup vs baseline: 1.7392x; 1.0820x over previous
#include <cuda_runtime.h>
#include <cuda_bf16.h>
#include <cstdint>

// Problem constants
// B=4, C=64, H=W=64, PS=4, PD=1, UFSTRIDE=2, STRIDE=1, SCALE=10
// Factorization: T[u,v,ys,xs] = sum_c bn[c,u,v] * f[c,ys,xs]   (GEMM, K=64, bf16 3-split)
//   cos[ly,lx,y,x] = sum_{dy,dx} T[cl(2ly+dy-1), cl(2lx+dx-1), cl(y+dy-1), cl(x+dx-1)]
// stage1 (dx) fused into GEMM epilogue; stage2 (dy) separate; fuse passes composed
// into one division-free 9-tap kernel; softmax is max-free.
// GEMM: BM=128, BN=128, warp tile 64x32 (acc 64 regs) -> 2 CTAs/SM.

#define NB    4
#define NC    64
#define LL    1024
#define PP    3969
#define CSTR  3972
#define SPA   4096
#define GKS   192          // 3-split K = 3*64
#define ROWB  384          // bytes per split row

#define BM    128
#define BN    128
#define NCHUNK 3
#define ABYTES (BM * 128)            // 16384
#define BBYTES (BN * 128)            // 16384
#define BUFBYTES (ABYTES + BBYTES)   // 32768
#define NSTAGE 2
#define PANES_BYTES (4 * 64 * 66 * 4) // 67584
#define SM_BYTES PANES_BYTES          // >= NSTAGE*BUFBYTES (65536)
#define S2_SMEM (4 * 4032 * 4)        // 64512

static __device__ float d_invn[NB * NC];
static __device__ __align__(16) __nv_bfloat16 d_A2[(size_t)NB * SPA * GKS];
static __device__ __align__(16) __nv_bfloat16 d_F2[(size_t)NB * SPA * GKS];
static __device__ float d_V  [(size_t)NB * 64 * 32 * 64 * 63];
static __device__ float d_cos [(size_t)NB * LL * CSTR];   // raw fused-input cos
static __device__ float d_tmp [(size_t)NB * LL * CSTR];   // masked fused cos
static __device__ float d_mmk [NB * LL];
static __device__ float d_mmp [NB * PP];
static __device__ float d_rcps[NB * PP];

__device__ __forceinline__ int clamp64(int v) { return min(max(v, 0), 63); }

__device__ __forceinline__ uint32_t smem_u32(const void* p) {
    uint32_t a;
    asm("{ .reg .u64 t; cvta.to.shared.u64 t, %1; cvt.u32.u64 %0, t; }" : "=r"(a) : "l"(p));
    return a;
}
__device__ __forceinline__ void cp_async16(uint32_t dst, const void* src) {
    asm volatile("cp.async.cg.shared.global [%0], [%1], 16;" :: "r"(dst), "l"(src) : "memory");
}
__device__ __forceinline__ void ldsm_x4(uint32_t* r, uint32_t addr) {
    asm volatile("ldmatrix.sync.aligned.m8n8.x4.shared.b16 {%0,%1,%2,%3}, [%4];"
                 : "=r"(r[0]), "=r"(r[1]), "=r"(r[2]), "=r"(r[3]) : "r"(addr));
}
__device__ __forceinline__ void mma_bf16(float* c, const uint32_t* a, const uint32_t* b) {
    asm volatile(
        "mma.sync.aligned.m16n8k16.row.col.f32.bf16.bf16.f32 "
        "{%0,%1,%2,%3}, {%4,%5,%6,%7}, {%8,%9}, {%0,%1,%2,%3};"
        : "+f"(c[0]), "+f"(c[1]), "+f"(c[2]), "+f"(c[3])
        : "r"(a[0]), "r"(a[1]), "r"(a[2]), "r"(a[3]), "r"(b[0]), "r"(b[1]));
}
__device__ __forceinline__ uint32_t swz(uint32_t base, int r, int c) {
    return base + r * 128 + ((c ^ (r & 7)) << 4);
}

// ---------------------------------------------------------------------------
// 1) per-(b,c) inverse L2 norm of b
// ---------------------------------------------------------------------------
__global__ void norm_kernel(const float* __restrict__ bsrc) {
    int bc = blockIdx.x;
    const float* src = bsrc + (size_t)bc * 4096;
    float s = 0.f;
    for (int i = threadIdx.x; i < 4096; i += 256) {
        float v = src[i];
        s += v * v;
    }
    __shared__ float sh[256];
    sh[threadIdx.x] = s;
    __syncthreads();
    for (int o = 128; o > 0; o >>= 1) {
        if (threadIdx.x < o) sh[threadIdx.x] += sh[threadIdx.x + o];
        __syncthreads();
    }
    if (threadIdx.x == 0) d_invn[bc] = 1.0f / sqrtf(sh[0] + 1e-8f);
}

// ---------------------------------------------------------------------------
// 2) build both bf16 splits: A2 (bn, [hi,hi,lo]) and F2 (f, [hi,lo,hi])
// ---------------------------------------------------------------------------
__global__ void build_AF_split(const float* __restrict__ bsrc,
                               const float* __restrict__ fsrc) {
    int idx = blockIdx.x * 256 + threadIdx.x;     // NB*4096*64
    int c = idx & 63;
    int s = (idx >> 6) & 4095;
    int b = idx >> 18;
    size_t row = ((size_t)b * SPA + s) * GKS;

    float a = bsrc[((size_t)(b * NC + c)) * 4096 + s] * d_invn[b * NC + c];
    __nv_bfloat16 ahi = __float2bfloat16(a);
    __nv_bfloat16 alo = __float2bfloat16(a - __bfloat162float(ahi));
    d_A2[row + c]       = ahi;
    d_A2[row + 64 + c]  = ahi;
    d_A2[row + 128 + c] = alo;

    float v = fsrc[((size_t)(b * NC + c)) * 4096 + s];
    __nv_bfloat16 fhi = __float2bfloat16(v);
    __nv_bfloat16 flo = __float2bfloat16(v - __bfloat162float(fhi));
    d_F2[row + c]       = fhi;
    d_F2[row + 64 + c]  = flo;
    d_F2[row + 128 + c] = fhi;
}

// ---------------------------------------------------------------------------
// 3) mask means, merged
// ---------------------------------------------------------------------------
__global__ void masks_kernel(const float* __restrict__ mask) {
    int p = blockIdx.x * 256 + threadIdx.x;
    int b = blockIdx.y;
    const float* m = mask + (size_t)b * 4096;
    if (p < PP) {
        int y = p / 63, x = p - 63 * y;
        float s = 0.f;
        #pragma unroll
        for (int i = 0; i < 4; i++)
            #pragma unroll
            for (int j = 0; j < 4; j++)
                s += 1.0f - m[clamp64(y + i - 1) * 64 + clamp64(x + j - 1)];
        d_mmp[b * PP + p] = s * 0.0625f;
    }
    if (p < LL) {
        int ly = p >> 5, lx = p & 31;
        float s = 0.f;
        #pragma unroll
        for (int i = 0; i < 4; i++)
            #pragma unroll
            for (int j = 0; j < 4; j++)
                s += 1.0f - m[clamp64(2 * ly + i - 1) * 64 + clamp64(2 * lx + j - 1)];
        d_mmk[b * LL + p] = s * 0.0625f;
    }
}

// ---------------------------------------------------------------------------
// 4) bf16 3-split GEMM + fused dx-stencil epilogue -> V
//    8 warps: wm=wid>>2 (M 64), wn=wid&3 (N 32). 2 CTAs/SM.
// ---------------------------------------------------------------------------
__global__ void __launch_bounds__(256, 2)
gemm_V_kernel() {
    extern __shared__ char smem[];
    const uint32_t sb = smem_u32(smem);
    const int tid  = threadIdx.x;
    const int wid  = tid >> 5;
    const int lane = tid & 31;
    const int wm   = wid >> 2;        // 0..1
    const int wn   = wid & 3;         // 0..3
    const int bI = blockIdx.z;
    const int m0 = blockIdx.y * BM;
    const int n0 = blockIdx.x * BN;

    const char* Ag = (const char*)d_A2 + ((size_t)bI * SPA + m0) * ROWB;
    const char* Bg = (const char*)d_F2 + ((size_t)bI * SPA + n0) * ROWB;

    float acc[4][4][4];
    #pragma unroll
    for (int mt = 0; mt < 4; mt++)
        #pragma unroll
        for (int nt = 0; nt < 4; nt++)
            #pragma unroll
            for (int e = 0; e < 4; e++) acc[mt][nt][e] = 0.f;

    const int ar = wm * 64 + (lane & 15);
    const int ac = (lane >> 4);
    const int br = wn * 32 + (lane & 7) + ((lane >> 4) << 3);
    const int bc = (lane >> 3) & 1;

    auto load_chunk = [&](int ch, int buf) {
        const uint32_t ab = sb + buf * BUFBYTES;
        const uint32_t bb = ab + ABYTES;
        const size_t koff = (size_t)ch * 128;
        #pragma unroll
        for (int i = 0; i < 4; i++) {
            int idx = i * 256 + tid;
            int r = idx >> 3, c = idx & 7;
            cp_async16(swz(ab, r, c), Ag + (size_t)r * ROWB + koff + c * 16);
        }
        #pragma unroll
        for (int i = 0; i < 4; i++) {
            int idx = i * 256 + tid;
            int r = idx >> 3, c = idx & 7;
            cp_async16(swz(bb, r, c), Bg + (size_t)r * ROWB + koff + c * 16);
        }
        asm volatile("cp.async.commit_group;" ::: "memory");
    };

    load_chunk(0, 0);
    load_chunk(1, 1);

    int buf = 0;
    for (int ch = 0; ch < NCHUNK; ch++) {
        if (ch < NCHUNK - 1) asm volatile("cp.async.wait_group 1;" ::: "memory");
        else                 asm volatile("cp.async.wait_group 0;" ::: "memory");
        __syncthreads();

        const uint32_t ab = sb + buf * BUFBYTES;
        const uint32_t bb = ab + ABYTES;
        #pragma unroll
        for (int ks = 0; ks < 4; ks++) {
            uint32_t afr[4][4];
            #pragma unroll
            for (int mt = 0; mt < 4; mt++)
                ldsm_x4(afr[mt], swz(ab, ar + mt * 16, ks * 2 + ac));
            uint32_t bfr[4][2];
            #pragma unroll
            for (int pp = 0; pp < 2; pp++) {
                uint32_t t[4];
                ldsm_x4(t, swz(bb, br + pp * 16, ks * 2 + bc));
                bfr[2 * pp][0] = t[0]; bfr[2 * pp][1] = t[1];
                bfr[2 * pp + 1][0] = t[2]; bfr[2 * pp + 1][1] = t[3];
            }
            #pragma unroll
            for (int mt = 0; mt < 4; mt++)
                #pragma unroll
                for (int nt = 0; nt < 4; nt++)
                    mma_bf16(acc[mt][nt], afr[mt], bfr[nt]);
        }
        __syncthreads();
        if (ch + NSTAGE < NCHUNK) load_chunk(ch + NSTAGE, buf);
        buf ^= 1;
    }
    __syncthreads();

    // fused stage1 epilogue.
    // pane pw = wm*2 + (wn>>1) holds T[u, v 0..63, ys, xs 0..63]; the two warps
    // with the same (wm, wn>>1) write xs halves (wn&1), then jointly stencil.
    float* W = (float*)smem + (wm * 2 + (wn >> 1)) * (64 * 66);
    const int xsh = (wn & 1) * 32;
    #pragma unroll
    for (int mt = 0; mt < 4; mt++) {
        int v0 = mt * 16 + (lane >> 2);
        #pragma unroll
        for (int nt = 0; nt < 4; nt++) {
            int xs = xsh + nt * 8 + 2 * (lane & 3);
            *(float2*)&W[v0 * 66 + xs]       = make_float2(acc[mt][nt][0], acc[mt][nt][1]);
            *(float2*)&W[(v0 + 8) * 66 + xs] = make_float2(acc[mt][nt][2], acc[mt][nt][3]);
        }
    }
    __syncthreads();

    const int u  = (m0 >> 6) + wm;
    const int ys = (n0 >> 6) + (wn >> 1);
    float* Vout = d_V + (((size_t)(bI * 64 + u) * 32) * 64 + ys) * 63;
    const int lx0 = (wn & 1) * 16;
    const int xA = lane;
    const int xB = lane + 32;
    #pragma unroll 4
    for (int li = 0; li < 16; li++) {
        int lx = lx0 + li;
        const float* r0 = W + clamp64(2 * lx - 1) * 66;
        const float* r1 = W + (2 * lx) * 66;
        const float* r2 = W + (2 * lx + 1) * 66;
        const float* r3 = W + clamp64(2 * lx + 2) * 66;
        float* vrow = Vout + (size_t)lx * 4032;
        vrow[xA] = r0[max(xA - 1, 0)] + r1[xA] + r2[xA + 1] + r3[min(xA + 2, 63)];
        if (lane < 31)
            vrow[xB] = r0[xB - 1] + r1[xB] + r2[xB + 1] + r3[min(xB + 2, 63)];
    }
}

// ---------------------------------------------------------------------------
// 5) stage2: cos[b][ly*32+lx][y*63+x] = sum_dy V[cl(2ly+dy-1)][lx][cl(y+dy-1)][x]
// ---------------------------------------------------------------------------
__global__ void stage2_kernel() {
    extern __shared__ float pl[];          // [4][4032]
    int lx = blockIdx.x, ly = blockIdx.y, b = blockIdx.z;
    int tid = threadIdx.x;
    #pragma unroll
    for (int dy = 0; dy < 4; dy++) {
        int u = clamp64(2 * ly + dy - 1);
        const float* Vp = d_V + (((size_t)(b * 64 + u) * 32 + lx) * 64) * 63;
        for (int idx = tid; idx < 4032; idx += 256)
            pl[dy * 4032 + idx] = Vp[idx];
    }
    __syncthreads();
    float* Crow = d_cos + ((size_t)(b * LL + ly * 32 + lx)) * CSTR;
    for (int o = tid; o < 63 * 63; o += 256) {
        int y = o / 63, x = o - y * 63;
        float s = 0.f;
        #pragma unroll
        for (int dy = 0; dy < 4; dy++)
            s += pl[dy * 4032 + clamp64(y + dy - 1) * 63 + x];
        Crow[o] = s;
    }
}

// ---------------------------------------------------------------------------
// 6) fused 9-tap pass (pass2 ∘ pass1) + mask, d_cos -> d_tmp  (division-free)
// ---------------------------------------------------------------------------
__global__ void fused_pass_kernel() {
    int q = blockIdx.x * 256 + threadIdx.x;
    if (q >= PP) return;
    int br = blockIdx.y;
    int b = br >> 10;
    int r = br & 1023;
    int ly = r >> 5, lx = r & 31;
    int y = q / 63, x = q - 63 * y;
    const float* cb = d_cos + (size_t)b * LL * CSTR;
    float s = 0.f;
    #pragma unroll
    for (int d2 = -1; d2 <= 1; d2++) {
        // transposed row index
        bool vR; int rf;
        int lyd = ly + d2;
        if (lyd >= 0 && lyd < 32) { vR = true;      rf = r + 32 * d2; }
        else if (lyd < 0)         { vR = (lx > 0);  rf = 992 + lx - 1; }
        else                      { vR = (lx < 31); rf = lx + 1; }
        // transposed col index
        bool vC; int cf;
        int yd = y + d2;
        if (yd >= 0 && yd < 63) { vC = true;      cf = q + 63 * d2; }
        else if (yd < 0)        { vC = (x > 0);   cf = 3906 + x - 1; }
        else                    { vC = (x < 62);  cf = x + 1; }
        if (vR && vC) {
            s += cb[(size_t)rf * CSTR + cf];
            if (rf > 0 && cf > 0)         s += cb[(size_t)(rf - 1) * CSTR + cf - 1];
            if (rf < 1023 && cf < PP - 1) s += cb[(size_t)(rf + 1) * CSTR + cf + 1];
        }
    }
    float mk = d_mmk[b * LL + r];
    float mp = d_mmp[b * PP + q];
    float mm = ((mk > mp && mp > 0.5f) || (mk == 1.0f)) ? 1.0f : 0.0f;
    d_tmp[(size_t)br * CSTR + q] = s * mm;
}

// ---------------------------------------------------------------------------
// 7) softmax sum (max-free; logits are 10*cosF, far from overflow; masked
//    entries contribute e^0=1 so the sum cannot underflow)
// ---------------------------------------------------------------------------
__global__ void smax_sum_kernel() {
    int b  = blockIdx.y;
    int pl = threadIdx.x & 31;
    int lt = threadIdx.x >> 5;
    int p  = blockIdx.x * 32 + pl;
    float s = 0.f;
    if (p < PP) {
        const float* cf = d_tmp + (size_t)b * LL * CSTR + p;
        for (int l = lt; l < LL; l += 8)
            s += __expf(10.0f * cf[(size_t)l * CSTR]);
    }
    __shared__ float shs[8][32];
    shs[lt][pl] = s;
    __syncthreads();
    if (lt == 0 && p < PP) {
        float S = 0.f;
        #pragma unroll
        for (int t = 0; t < 8; t++) S += shs[t][pl];
        d_rcps[b * PP + p] = 1.0f / S;
    }
}

// ---------------------------------------------------------------------------
// 8) softmax write
// ---------------------------------------------------------------------------
__global__ void smax_write_kernel(float* __restrict__ out) {
    int q = blockIdx.x * 256 + threadIdx.x;
    if (q >= PP) return;
    int bl = blockIdx.y;
    int b = bl >> 10;
    float x = 10.0f * d_tmp[(size_t)bl * CSTR + q];
    out[(size_t)bl * PP + q] = __expf(x) * d_rcps[b * PP + q];
}

// ---------------------------------------------------------------------------
extern "C" void kernel_launch(void* const* d_in, const int* in_sizes, int n_in,
                              void* d_out, int out_size) {
    const float* f    = (const float*)d_in[0];
    const float* bsrc = (const float*)d_in[1];
    const float* mask = (const float*)d_in[2];
    float* out = (float*)d_out;

    cudaFuncSetAttribute(gemm_V_kernel,
                         cudaFuncAttributeMaxDynamicSharedMemorySize, SM_BYTES);
    cudaFuncSetAttribute(stage2_kernel,
                         cudaFuncAttributeMaxDynamicSharedMemorySize, S2_SMEM);

    norm_kernel<<<NB * NC, 256>>>(bsrc);
    build_AF_split<<<(NB * SPA * NC) / 256, 256>>>(bsrc, f);
    masks_kernel<<<dim3((PP + 255) / 256, NB), 256>>>(mask);

    gemm_V_kernel<<<dim3(SPA / BN, SPA / BM, NB), 256, SM_BYTES>>>();

    stage2_kernel<<<dim3(32, 32, NB), 256, S2_SMEM>>>();

    dim3 g2((PP + 255) / 256, NB * LL);
    fused_pass_kernel<<<g2, 256>>>();

    smax_sum_kernel<<<dim3((PP + 31) / 32, NB), 256>>>();
    smax_write_kernel<<<g2, 256>>>(out);
}